// round 7
// baseline (speedup 1.0000x reference)
#include <cuda_runtime.h>
#include <cuda_bf16.h>
#include <math.h>
#include <stdint.h>

// ---------------- problem constants ----------------
#define L_   4096
#define DM   2048          // D_MODEL
#define DI   4096          // D_INNER
#define NH   64            // N_HEADS
#define DH   64            // D_HEAD
#define NS   128           // D_STATE
#define CD   4352          // CONV_DIM
#define DPJ  8512          // D_IN_PROJ
#define DPJA 8704          // padded to 68*128 for GEMM tiles
#define CK   256           // CHUNK
#define NCH  32            // total chunks
#define RW   8192          // total rows = B*L

// ---------------- scratch (device globals; no allocations) ----------------
__device__ float g_zx[(size_t)RW * DPJA];
__device__ float g_xBC[(size_t)RW * CD];
__device__ float g_dt[RW * NH];
__device__ float g_dacs[RW * NH];
__device__ float g_CBt[NCH * CK * CK];
__device__ float g_states[(size_t)NCH * NH * DH * NS];
__device__ float g_prev[(size_t)NCH * NH * DH * NS];
__device__ float g_y[(size_t)RW * DI];
// int8 two-digit operands + per-row scales
__device__ int8_t g_u1[(size_t)RW * DM],   g_u2[(size_t)RW * DM];
__device__ int8_t g_wi1[(size_t)DPJA * DM], g_wi2[(size_t)DPJA * DM];
__device__ int8_t g_y1[(size_t)RW * DI],   g_y2[(size_t)RW * DI];
__device__ int8_t g_wo1[(size_t)DM * DI],  g_wo2[(size_t)DM * DI];
__device__ float g_su[RW], g_swi[DPJA], g_sy[RW], g_swo[DM];

// ================= PTX helpers (portable, compute_103-safe) =================
__device__ __forceinline__ uint32_t smem_u32(const void* p) {
    uint32_t a;
    asm("{ .reg .u64 t; cvta.to.shared.u64 t, %1; cvt.u32.u64 %0, t; }" : "=r"(a) : "l"(p));
    return a;
}
#define CPA16(dst, src) \
    asm volatile("cp.async.cg.shared.global [%0], [%1], 16;" :: "r"(dst), "l"(src) : "memory")

#define LDSM4(r, adr)                                                            \
    asm volatile("ldmatrix.sync.aligned.m8n8.x4.shared.b16 {%0,%1,%2,%3}, [%4];" \
        : "=r"((r)[0]), "=r"((r)[1]), "=r"((r)[2]), "=r"((r)[3]) : "r"(adr))

#define MMAI8(c, a, b0, b1)                                                      \
    asm volatile("mma.sync.aligned.m16n8k32.row.col.s32.s8.s8.s32 "              \
        "{%0,%1,%2,%3}, {%4,%5,%6,%7}, {%8,%9}, {%0,%1,%2,%3};"                  \
        : "+r"((c)[0]), "+r"((c)[1]), "+r"((c)[2]), "+r"((c)[3])                  \
        : "r"((a)[0]), "r"((a)[1]), "r"((a)[2]), "r"((a)[3]), "r"(b0), "r"(b1))

// ================= fp32 -> two int8 digits, per-row scale =================
// x = s*(a1 + a2/256), s = rowmax/127. Rows >= rows_src become zeros (scale 0).
__global__ __launch_bounds__(256) void quant2_kernel(
    const float* __restrict__ src, int8_t* __restrict__ d1, int8_t* __restrict__ d2,
    float* __restrict__ scl, int K, int rows_src)
{
    const int row = blockIdx.x;
    const int tid = threadIdx.x;
    int8_t* p1 = d1 + (size_t)row * K;
    int8_t* p2 = d2 + (size_t)row * K;
    const int K4 = K / 4;
    if (row >= rows_src) {
        for (int k = tid; k < K4; k += 256) {
            ((int*)p1)[k] = 0; ((int*)p2)[k] = 0;
        }
        if (tid == 0) scl[row] = 0.f;
        return;
    }
    const float4* s4 = (const float4*)(src + (size_t)row * K);
    float mx = 0.f;
    for (int k = tid; k < K4; k += 256) {
        float4 v = s4[k];
        mx = fmaxf(mx, fmaxf(fmaxf(fabsf(v.x), fabsf(v.y)), fmaxf(fabsf(v.z), fabsf(v.w))));
    }
    __shared__ float red[8];
#pragma unroll
    for (int o = 16; o > 0; o >>= 1) mx = fmaxf(mx, __shfl_xor_sync(0xffffffffu, mx, o));
    if ((tid & 31) == 0) red[tid >> 5] = mx;
    __syncthreads();
    mx = red[0];
#pragma unroll
    for (int q = 1; q < 8; q++) mx = fmaxf(mx, red[q]);
    const float sinv = (mx > 0.f) ? 127.f / mx : 0.f;
    if (tid == 0) scl[row] = (mx > 0.f) ? mx / 127.f : 0.f;

    for (int k = tid; k < K4; k += 256) {
        float4 v = s4[k];
        float f[4] = {v.x, v.y, v.z, v.w};
        signed char q1[4], q2[4];
#pragma unroll
        for (int e = 0; e < 4; e++) {
            float vv = f[e] * sinv;
            int a1 = __float2int_rn(vv);
            float r = (vv - (float)a1) * 256.f;
            int a2 = __float2int_rn(r);
            a2 = max(-127, min(127, a2));
            q1[e] = (signed char)a1; q2[e] = (signed char)a2;
        }
        ((char4*)p1)[k] = make_char4(q1[0], q1[1], q1[2], q1[3]);
        ((char4*)p2)[k] = make_char4(q2[0], q2[1], q2[2], q2[3]);
    }
}

// ================= int8 two-digit emulated NT GEMM =================
// C[m][n] = sA[m]*sB[n]*(sum a1b1 + (sum a1b2 + a2b1)/256)
// CTA tile 128x128, K-step 64 bytes, 3-stage cp.async, 8 warps (2M x 4N).
#define QSTAGES 3
#define QROWB 80
#define QA_BYTES (128 * QROWB)
#define QSTAGE_BYTES (4 * QA_BYTES)
#define QGEMM_SMEM (QSTAGES * QSTAGE_BYTES)   // 122880 bytes

__global__ __launch_bounds__(256, 1) void gemm_i8(
    const int8_t* __restrict__ A1, const int8_t* __restrict__ A2,
    const int8_t* __restrict__ B1, const int8_t* __restrict__ B2,
    const float* __restrict__ sA, const float* __restrict__ sB,
    float* __restrict__ C, int Ktot, int ldc)
{
    extern __shared__ int8_t qsm[];
    const int tid = threadIdx.x;
    const int wid = tid >> 5;
    const int lane = tid & 31;

    const int m0 = blockIdx.y * 128;
    const int n0 = blockIdx.x * 128;

    const int lrow = tid >> 2;           // 0..63
    const int lcb  = (tid & 3) * 16;     // byte offset within 64-byte K-slab

    const int8_t* a1p = A1 + (size_t)m0 * Ktot;
    const int8_t* a2p = A2 + (size_t)m0 * Ktot;
    const int8_t* b1p = B1 + (size_t)n0 * Ktot;
    const int8_t* b2p = B2 + (size_t)n0 * Ktot;

    auto load_stage = [&](int s, int k0) {
        int8_t* st = qsm + s * QSTAGE_BYTES;
#pragma unroll
        for (int q = 0; q < 2; q++) {
            int row = lrow + q * 64;
            uint32_t d = smem_u32(st + row * QROWB + lcb);
            CPA16(d + 0 * QA_BYTES, a1p + (size_t)row * Ktot + k0 + lcb);
            CPA16(d + 1 * QA_BYTES, a2p + (size_t)row * Ktot + k0 + lcb);
            CPA16(d + 2 * QA_BYTES, b1p + (size_t)row * Ktot + k0 + lcb);
            CPA16(d + 3 * QA_BYTES, b2p + (size_t)row * Ktot + k0 + lcb);
        }
        asm volatile("cp.async.commit_group;" ::: "memory");
    };

    // warp tiling: 2 warps along M (64 rows), 4 along N (32 cols)
    const int wm = (wid & 1) * 64;
    const int wn = (wid >> 1) * 32;
    const int fr = lane & 15;
    const int fcb = (lane >> 4) * 16;    // ldmatrix column-half (bytes)

    int c1[4][4][4], c2[4][4][4];
#pragma unroll
    for (int a = 0; a < 4; a++)
#pragma unroll
        for (int b = 0; b < 4; b++)
#pragma unroll
            for (int c = 0; c < 4; c++) { c1[a][b][c] = 0; c2[a][b][c] = 0; }

    const int KT = Ktot / 64;
    load_stage(0, 0);
    load_stage(1, 64);

    int cur = 0, nxt = 2;
    for (int kt = 0; kt < KT; kt++) {
        if (kt < KT - 1) {
            asm volatile("cp.async.wait_group 1;" ::: "memory");
        } else {
            asm volatile("cp.async.wait_group 0;" ::: "memory");
        }
        __syncthreads();
        if (kt + 2 < KT) load_stage(nxt, (kt + 2) * 64);   // buffer consumed at kt-1: race-free

        const int8_t* st = qsm + cur * QSTAGE_BYTES;
#pragma unroll
        for (int kk = 0; kk < 2; kk++) {
            const int kof = kk * 32;
            uint32_t qa1[4][4], qa2[4][4];
#pragma unroll
            for (int mb = 0; mb < 4; mb++) {
                uint32_t adr = smem_u32(st + (wm + mb * 16 + fr) * QROWB + kof + fcb);
                LDSM4(qa1[mb], adr);
                LDSM4(qa2[mb], adr + QA_BYTES);
            }
            uint32_t qb1[2][4], qb2[2][4];
#pragma unroll
            for (int nb2 = 0; nb2 < 2; nb2++) {
                uint32_t adr = smem_u32(st + 2 * QA_BYTES + (wn + nb2 * 16 + fr) * QROWB + kof + fcb);
                LDSM4(qb1[nb2], adr);
                LDSM4(qb2[nb2], adr + QA_BYTES);
            }
#pragma unroll
            for (int mb = 0; mb < 4; mb++)
#pragma unroll
                for (int nb = 0; nb < 4; nb++)
                    MMAI8(c1[mb][nb], qa1[mb], qb1[nb >> 1][nb & 1], qb1[nb >> 1][(nb & 1) + 2]);
#pragma unroll
            for (int mb = 0; mb < 4; mb++)
#pragma unroll
                for (int nb = 0; nb < 4; nb++)
                    MMAI8(c2[mb][nb], qa1[mb], qb2[nb >> 1][nb & 1], qb2[nb >> 1][(nb & 1) + 2]);
#pragma unroll
            for (int mb = 0; mb < 4; mb++)
#pragma unroll
                for (int nb = 0; nb < 4; nb++)
                    MMAI8(c2[mb][nb], qa2[mb], qb1[nb >> 1][nb & 1], qb1[nb >> 1][(nb & 1) + 2]);
        }
        cur = (cur == 2) ? 0 : cur + 1;
        nxt = (nxt == 2) ? 0 : nxt + 1;
    }

    // epilogue: dequant
    const int er = lane >> 2;
    const int ec = (lane & 3) * 2;
    const float inv256 = 0.00390625f;
#pragma unroll
    for (int mb = 0; mb < 4; mb++) {
        const int r0 = m0 + wm + mb * 16 + er;
        const float sa0 = sA[r0], sa1 = sA[r0 + 8];
#pragma unroll
        for (int nb = 0; nb < 4; nb++) {
            const int col = n0 + wn + nb * 8 + ec;
            const float sb0 = sB[col], sb1 = sB[col + 1];
            float v0 = sa0 * sb0 * ((float)c1[mb][nb][0] + (float)c2[mb][nb][0] * inv256);
            float v1 = sa0 * sb1 * ((float)c1[mb][nb][1] + (float)c2[mb][nb][1] * inv256);
            float v2 = sa1 * sb0 * ((float)c1[mb][nb][2] + (float)c2[mb][nb][2] * inv256);
            float v3 = sa1 * sb1 * ((float)c1[mb][nb][3] + (float)c2[mb][nb][3] * inv256);
            *(float2*)(C + (size_t)r0 * ldc + col)       = make_float2(v0, v1);
            *(float2*)(C + (size_t)(r0 + 8) * ldc + col) = make_float2(v2, v3);
        }
    }
}

// ---------------- fp32 NT SGEMM (kept for small per-chunk C@B^T) ----------------
__global__ __launch_bounds__(256) void sgemm_nt(
    const float* __restrict__ A, const float* __restrict__ Bm, float* __restrict__ C,
    int M, int N, int K, int lda, int ldb, int ldc,
    long sA, long sB, long sC)
{
    const float* Ab = A + (long)blockIdx.z * sA;
    const float* Bb = Bm + (long)blockIdx.z * sB;
    float* Cb = C + (long)blockIdx.z * sC;

    __shared__ float As[16][128];
    __shared__ float Bs[16][128];

    const int tid = threadIdx.x;
    const int m0 = blockIdx.y * 128;
    const int n0 = blockIdx.x * 128;
    const int tx = tid & 15;
    const int ty = tid >> 4;

    const int lrow = tid >> 1;
    const int lk = (tid & 1) * 8;
    const float* Aload = Ab + (long)(m0 + lrow) * lda + lk;
    const float* Bload = Bb + (long)(n0 + lrow) * ldb + lk;
    const bool bvalid = (n0 + lrow) < N;

    float acc[8][8];
#pragma unroll
    for (int i = 0; i < 8; i++)
#pragma unroll
        for (int j = 0; j < 8; j++) acc[i][j] = 0.0f;

    float4 a0 = *(const float4*)(Aload);
    float4 a1 = *(const float4*)(Aload + 4);
    float4 b0 = make_float4(0.f,0.f,0.f,0.f), b1 = make_float4(0.f,0.f,0.f,0.f);
    if (bvalid) { b0 = *(const float4*)(Bload); b1 = *(const float4*)(Bload + 4); }

    for (int k0 = 0; k0 < K; k0 += 16) {
        As[lk+0][lrow] = a0.x; As[lk+1][lrow] = a0.y; As[lk+2][lrow] = a0.z; As[lk+3][lrow] = a0.w;
        As[lk+4][lrow] = a1.x; As[lk+5][lrow] = a1.y; As[lk+6][lrow] = a1.z; As[lk+7][lrow] = a1.w;
        Bs[lk+0][lrow] = b0.x; Bs[lk+1][lrow] = b0.y; Bs[lk+2][lrow] = b0.z; Bs[lk+3][lrow] = b0.w;
        Bs[lk+4][lrow] = b1.x; Bs[lk+5][lrow] = b1.y; Bs[lk+6][lrow] = b1.z; Bs[lk+7][lrow] = b1.w;
        __syncthreads();
        if (k0 + 16 < K) {
            a0 = *(const float4*)(Aload + k0 + 16);
            a1 = *(const float4*)(Aload + k0 + 20);
            if (bvalid) {
                b0 = *(const float4*)(Bload + k0 + 16);
                b1 = *(const float4*)(Bload + k0 + 20);
            }
        }
#pragma unroll
        for (int kk = 0; kk < 16; kk++) {
            float av[8], bv[8];
            *(float4*)&av[0] = *(const float4*)&As[kk][ty*8];
            *(float4*)&av[4] = *(const float4*)&As[kk][ty*8+4];
            *(float4*)&bv[0] = *(const float4*)&Bs[kk][tx*8];
            *(float4*)&bv[4] = *(const float4*)&Bs[kk][tx*8+4];
#pragma unroll
            for (int i = 0; i < 8; i++)
#pragma unroll
                for (int j = 0; j < 8; j++) acc[i][j] += av[i]*bv[j];
        }
        __syncthreads();
    }

#pragma unroll
    for (int i = 0; i < 8; i++) {
        int row = m0 + ty*8 + i;
        float* Crow = Cb + (long)row*ldc + n0 + tx*8;
        if (n0 + tx*8 + 4 <= N) {
            *(float4*)Crow = make_float4(acc[i][0],acc[i][1],acc[i][2],acc[i][3]);
        }
        if (n0 + tx*8 + 8 <= N) {
            *(float4*)(Crow+4) = make_float4(acc[i][4],acc[i][5],acc[i][6],acc[i][7]);
        }
    }
}

// ---------------- causal depthwise conv (width 4) + SiLU ----------------
__global__ void conv_silu_kernel(const float* __restrict__ conv_w,
                                 const float* __restrict__ conv_b)
{
    int cc = blockIdx.x * 256 + threadIdx.x;
    int r = blockIdx.y;
    int l = r & (L_ - 1);
    float acc = conv_b[cc];
    const float* col = g_zx + (size_t)r * DPJA + DI + cc;
#pragma unroll
    for (int w = 0; w < 4; w++) {
        int lp = l - 3 + w;
        if (lp >= 0) acc += col[(long)(w - 3) * DPJA] * conv_w[cc*4 + w];
    }
    float s = acc / (1.0f + __expf(-acc));
    g_xBC[(size_t)r * CD + cc] = s;
}

// ---------------- dt softplus + within-chunk cumsum of dt*A (parallel scan) ----------------
__global__ __launch_bounds__(256) void dt_cumsum_kernel(const float* __restrict__ dt_bias,
                                                        const float* __restrict__ A_log)
{
    __shared__ float wsum[8];
    const int chunk = blockIdx.x;
    const int h = blockIdx.y;
    const int i = threadIdx.x;
    const int lane = i & 31, wid = i >> 5;
    const int r = chunk * CK + i;

    float Ahd = -expf(A_log[h]);
    float x = g_zx[(size_t)r * DPJA + DI + CD + h] + dt_bias[h];
    float dt = fmaxf(x, 0.f) + log1pf(expf(-fabsf(x)));
    g_dt[r*NH + h] = dt;

    float v = dt * Ahd;
#pragma unroll
    for (int o = 1; o < 32; o <<= 1) {
        float n = __shfl_up_sync(0xffffffffu, v, o);
        if (lane >= o) v += n;
    }
    if (lane == 31) wsum[wid] = v;
    __syncthreads();
    float add = 0.f;
#pragma unroll
    for (int wq = 0; wq < 8; wq++) {
        float ws = wsum[wq];
        add += (wq < wid) ? ws : 0.f;
    }
    g_dacs[r*NH + h] = v + add;
}

// ---------------- per-(chunk,head) state accumulation ----------------
__global__ __launch_bounds__(256) void states_kernel()
{
    int chunk = blockIdx.x;
    int h = blockIdx.y;
    int base = chunk * CK;
    int tid = threadIdx.x;

    __shared__ float ws[CK];
    __shared__ float xs[32*64];
    __shared__ float Bsh[32*128];

    {
        float dl = g_dacs[(base + CK - 1)*NH + h];
        float dv = g_dacs[(base + tid)*NH + h];
        ws[tid] = __expf(dl - dv) * g_dt[(base + tid)*NH + h];
    }

    const int tp = tid >> 5;
    const int tn = tid & 31;
    float acc[8][4];
#pragma unroll
    for (int a = 0; a < 8; a++)
#pragma unroll
        for (int b = 0; b < 4; b++) acc[a][b] = 0.f;

    for (int st = 0; st < 8; st++) {
        __syncthreads();
#pragma unroll
        for (int rep = 0; rep < 2; rep++) {
            int f = tid + rep*256;
            int row = f >> 4, c4 = f & 15;
            *(float4*)&xs[row*64 + c4*4] =
                *(const float4*)&g_xBC[(size_t)(base + st*32 + row)*CD + h*64 + c4*4];
        }
#pragma unroll
        for (int rep = 0; rep < 4; rep++) {
            int f = tid + rep*256;
            int row = f >> 5, c4 = f & 31;
            *(float4*)&Bsh[row*128 + c4*4] =
                *(const float4*)&g_xBC[(size_t)(base + st*32 + row)*CD + DI + c4*4];
        }
        __syncthreads();

        for (int s = 0; s < 32; s++) {
            float w = ws[st*32 + s];
            float4 bv = *(const float4*)&Bsh[s*128 + tn*4];
            float xw[8];
#pragma unroll
            for (int pp = 0; pp < 8; pp++) xw[pp] = w * xs[s*64 + tp + pp*8];
#pragma unroll
            for (int pp = 0; pp < 8; pp++) {
                acc[pp][0] += xw[pp]*bv.x;
                acc[pp][1] += xw[pp]*bv.y;
                acc[pp][2] += xw[pp]*bv.z;
                acc[pp][3] += xw[pp]*bv.w;
            }
        }
    }

    size_t obase = (size_t)(chunk*NH + h) * DH * NS;
#pragma unroll
    for (int pp = 0; pp < 8; pp++) {
        *(float4*)&g_states[obase + (size_t)(tp + pp*8)*NS + tn*4] =
            make_float4(acc[pp][0], acc[pp][1], acc[pp][2], acc[pp][3]);
    }
}

// ---------------- inter-chunk scan ----------------
__global__ void scan_kernel()
{
    int idx = blockIdx.x * 256 + threadIdx.x;
    int h = (idx >> 13) & 63;
    int b = idx >> 19;
    float s = 0.f;
    for (int c = 0; c < 16; c++) {
        size_t off = ((size_t)(b*16 + c)*NH + h)*DH*NS + (idx & 8191);
        g_prev[off] = s;
        float dec = __expf(g_dacs[(size_t)(b*L_ + c*CK + CK - 1)*NH + h]);
        s = s * dec + g_states[off];
    }
}

// ---------------- fused y = y_diag + y_off + Dp*x per (chunk, head) ----------------
#define Y_SMEM_BYTES ((256*64 + 128*68 + 256*36 + 256 + 256) * 4)
__global__ __launch_bounds__(256) void y_kernel(const float* __restrict__ Dp)
{
    extern __shared__ float sm[];
    float* xs    = sm;
    float* prevT = xs + 256*64;
    float* Cs    = prevT + 128*68;
    float* das   = Cs + 256*36;
    float* dts   = das + 256;

    int chunk = blockIdx.x;
    int h = blockIdx.y;
    int base = chunk * CK;
    int tid = threadIdx.x;

    int w = tid >> 5, lane = tid & 31;
    int rb = (w < 4) ? (2*w) : (7 - 2*(w - 4));
    int i = rb*32 + lane;

    {
        const float4* src = (const float4*)&g_xBC[(size_t)(base + i)*CD + h*64];
        float4* dst = (float4*)&xs[i*64];
#pragma unroll
        for (int q = 0; q < 16; q++) dst[q] = src[q];
    }
    das[i] = g_dacs[(base + i)*NH + h];
    dts[i] = g_dt[(base + i)*NH + h];
    {
        size_t pb = (size_t)(chunk*NH + h) * DH * NS;
#pragma unroll
        for (int e = 0; e < 32; e++) {
            int f = tid + e*256;
            int p = f >> 7, n = f & 127;
            prevT[n*68 + p] = g_prev[pb + f];
        }
    }
    __syncthreads();

    float dai = das[i];
    float dph = Dp[h];
    float acc[64];
    {
        const float4* xr = (const float4*)&xs[i*64];
#pragma unroll
        for (int q = 0; q < 16; q++) {
            float4 v = xr[q];
            acc[4*q+0] = dph*v.x; acc[4*q+1] = dph*v.y;
            acc[4*q+2] = dph*v.z; acc[4*q+3] = dph*v.w;
        }
    }

    const float* cb = g_CBt + (size_t)chunk * CK * CK;
    for (int j = 0; j <= i; j++) {
        float wgt = cb[j*CK + i] * __expf(dai - das[j]) * dts[j];
        const float4* xr = (const float4*)&xs[j*64];
#pragma unroll
        for (int q = 0; q < 16; q++) {
            float4 v = xr[q];
            acc[4*q+0] += wgt*v.x; acc[4*q+1] += wgt*v.y;
            acc[4*q+2] += wgt*v.z; acc[4*q+3] += wgt*v.w;
        }
    }

    float ei = __expf(dai);
    for (int nt = 0; nt < 4; nt++) {
        {
            const float4* src = (const float4*)&g_xBC[(size_t)(base + i)*CD + DI + NS + nt*32];
            float4* dst = (float4*)&Cs[i*36];
#pragma unroll
            for (int q = 0; q < 8; q++) dst[q] = src[q];
        }
        __syncthreads();
        for (int nn = 0; nn < 32; nn++) {
            float cv = ei * Cs[i*36 + nn];
            const float4* pr = (const float4*)&prevT[(nt*32 + nn)*68];
#pragma unroll
            for (int q = 0; q < 16; q++) {
                float4 v = pr[q];
                acc[4*q+0] += cv*v.x; acc[4*q+1] += cv*v.y;
                acc[4*q+2] += cv*v.z; acc[4*q+3] += cv*v.w;
            }
        }
        __syncthreads();
    }

    {
        float4* dst = (float4*)&g_y[(size_t)(base + i)*DI + h*64];
#pragma unroll
        for (int q = 0; q < 16; q++)
            dst[q] = make_float4(acc[4*q], acc[4*q+1], acc[4*q+2], acc[4*q+3]);
    }
}

// ---------------- gate (silu(z)) + RMSNorm ----------------
__global__ __launch_bounds__(256) void gate_norm_kernel(const float* __restrict__ norm_w)
{
    __shared__ float buf[DI];
    __shared__ float red[8];
    int r = blockIdx.x;
    int tid = threadIdx.x;
    float ss = 0.f;
#pragma unroll
    for (int e = 0; e < 16; e++) {
        int c = tid + e*256;
        float y = g_y[(size_t)r*DI + c];
        float z = g_zx[(size_t)r*DPJA + c];
        float g = y * (z / (1.f + __expf(-z)));
        buf[c] = g;
        ss += g*g;
    }
#pragma unroll
    for (int o = 16; o > 0; o >>= 1) ss += __shfl_xor_sync(0xffffffffu, ss, o);
    if ((tid & 31) == 0) red[tid >> 5] = ss;
    __syncthreads();
    float tot = 0.f;
#pragma unroll
    for (int q = 0; q < 8; q++) tot += red[q];
    float scale = rsqrtf(tot / (float)DI + 1e-5f);
#pragma unroll
    for (int e = 0; e < 16; e++) {
        int c = tid + e*256;
        g_y[(size_t)r*DI + c] = buf[c] * scale * norm_w[c];
    }
}

// ---------------- launch ----------------
extern "C" void kernel_launch(void* const* d_in, const int* in_sizes, int n_in,
                              void* d_out, int out_size)
{
    const float* u       = (const float*)d_in[0];
    const float* W_in    = (const float*)d_in[1];
    const float* conv_w  = (const float*)d_in[2];
    const float* conv_b  = (const float*)d_in[3];
    const float* dt_bias = (const float*)d_in[4];
    const float* A_log   = (const float*)d_in[5];
    const float* Dp      = (const float*)d_in[6];
    const float* norm_w  = (const float*)d_in[7];
    const float* W_out   = (const float*)d_in[8];
    float* out = (float*)d_out;

    float *zx, *xbc, *cbt, *y;
    int8_t *u1, *u2, *wi1, *wi2, *y1, *y2, *wo1, *wo2;
    float *su, *swi, *sy, *swo;
    cudaGetSymbolAddress((void**)&zx,  g_zx);
    cudaGetSymbolAddress((void**)&xbc, g_xBC);
    cudaGetSymbolAddress((void**)&cbt, g_CBt);
    cudaGetSymbolAddress((void**)&y,   g_y);
    cudaGetSymbolAddress((void**)&u1,  g_u1);
    cudaGetSymbolAddress((void**)&u2,  g_u2);
    cudaGetSymbolAddress((void**)&wi1, g_wi1);
    cudaGetSymbolAddress((void**)&wi2, g_wi2);
    cudaGetSymbolAddress((void**)&y1,  g_y1);
    cudaGetSymbolAddress((void**)&y2,  g_y2);
    cudaGetSymbolAddress((void**)&wo1, g_wo1);
    cudaGetSymbolAddress((void**)&wo2, g_wo2);
    cudaGetSymbolAddress((void**)&su,  g_su);
    cudaGetSymbolAddress((void**)&swi, g_swi);
    cudaGetSymbolAddress((void**)&sy,  g_sy);
    cudaGetSymbolAddress((void**)&swo, g_swo);

    cudaFuncSetAttribute(y_kernel, cudaFuncAttributeMaxDynamicSharedMemorySize, Y_SMEM_BYTES);
    cudaFuncSetAttribute(gemm_i8, cudaFuncAttributeMaxDynamicSharedMemorySize, QGEMM_SMEM);

    // quantize inputs for GEMM1
    quant2_kernel<<<RW, 256>>>(u, u1, u2, su, DM, RW);
    quant2_kernel<<<DPJA, 256>>>(W_in, wi1, wi2, swi, DM, DPJ);

    // 1) in-proj: zx[8192, 8704(pad)] = u @ W_in^T  (int8 two-digit emulated)
    gemm_i8<<<dim3(DPJA/128, RW/128), 256, QGEMM_SMEM>>>(u1, u2, wi1, wi2, su, swi, zx, DM, DPJA);

    // 2) conv + silu
    conv_silu_kernel<<<dim3(CD/256, RW), 256>>>(conv_w, conv_b);

    // 3) dt softplus + per-chunk cumsum (parallel scan)
    dt_cumsum_kernel<<<dim3(NCH, NH), 256>>>(dt_bias, A_log);

    // 4) per-chunk CBt
    dim3 g2(2, 2, NCH);
    sgemm_nt<<<g2, 256>>>(xbc + DI, xbc + DI + NS, cbt,
                          CK, CK, NS, CD, CD, CK,
                          (long)CK*CD, (long)CK*CD, (long)CK*CK);

    // 5) states
    states_kernel<<<dim3(NCH, NH), 256>>>();

    // 6) inter-chunk scan
    scan_kernel<<<4096, 256>>>();

    // 7) fused y
    y_kernel<<<dim3(NCH, NH), 256, Y_SMEM_BYTES>>>(Dp);

    // 8) gate + RMSNorm
    gate_norm_kernel<<<RW, 256>>>(norm_w);

    // quantize for GEMM2
    quant2_kernel<<<RW, 256>>>(y, y1, y2, sy, DI, RW);
    quant2_kernel<<<DM, 256>>>(W_out, wo1, wo2, swo, DI, DM);

    // 9) out-proj: out[8192,2048] = y @ W_out^T  (int8 two-digit emulated)
    gemm_i8<<<dim3(DM/128, RW/128), 256, QGEMM_SMEM>>>(y1, y2, wo1, wo2, sy, swo, out, DI, DM);
}

// round 8
// speedup vs baseline: 2.4182x; 2.4182x over previous
#include <cuda_runtime.h>
#include <cuda_fp16.h>
#include <math.h>
#include <stdint.h>

// ---------------- problem constants ----------------
#define L_   4096
#define DM   2048          // D_MODEL
#define DI   4096          // D_INNER
#define NH   64            // N_HEADS
#define DH   64            // D_HEAD
#define NS   128           // D_STATE
#define CD   4352          // CONV_DIM
#define DPJ  8512          // D_IN_PROJ
#define DPJA 8704          // padded to 68*128 for GEMM tiles
#define CK   256           // CHUNK
#define NCH  32            // total chunks
#define RW   8192          // total rows = B*L

// ---------------- scratch (device globals; no allocations) ----------------
__device__ float g_zx[(size_t)RW * DPJA];
__device__ float g_xBC[(size_t)RW * CD];
__device__ float g_dt[RW * NH];
__device__ float g_dacs[RW * NH];
__device__ float g_CBt[NCH * CK * CK];
__device__ float g_states[(size_t)NCH * NH * DH * NS];
__device__ float g_prev[(size_t)NCH * NH * DH * NS];
__device__ float g_y[(size_t)RW * DI];
// fp16 operands: activations single fp16, weights double fp16 (value + residual)
__device__ __half g_uh[(size_t)RW * DM];
__device__ __half g_wi1[(size_t)DPJA * DM], g_wi2[(size_t)DPJA * DM];
__device__ __half g_yh[(size_t)RW * DI];
__device__ __half g_wo1[(size_t)DM * DI],  g_wo2[(size_t)DM * DI];

// ================= PTX helpers (portable, compute_103-safe) =================
__device__ __forceinline__ uint32_t smem_u32(const void* p) {
    uint32_t a;
    asm("{ .reg .u64 t; cvta.to.shared.u64 t, %1; cvt.u32.u64 %0, t; }" : "=r"(a) : "l"(p));
    return a;
}
#define CPA16(dst, src) \
    asm volatile("cp.async.cg.shared.global [%0], [%1], 16;" :: "r"(dst), "l"(src) : "memory")

#define LDSM4(r, adr)                                                            \
    asm volatile("ldmatrix.sync.aligned.m8n8.x4.shared.b16 {%0,%1,%2,%3}, [%4];" \
        : "=r"((r)[0]), "=r"((r)[1]), "=r"((r)[2]), "=r"((r)[3]) : "r"(adr))

#define MMAF16(c, a, b0, b1)                                                     \
    asm volatile("mma.sync.aligned.m16n8k16.row.col.f32.f16.f16.f32 "            \
        "{%0,%1,%2,%3}, {%4,%5,%6,%7}, {%8,%9}, {%0,%1,%2,%3};"                  \
        : "+f"((c)[0]), "+f"((c)[1]), "+f"((c)[2]), "+f"((c)[3])                  \
        : "r"((a)[0]), "r"((a)[1]), "r"((a)[2]), "r"((a)[3]), "r"(b0), "r"(b1))

// ================= conversion kernels =================
// fp32 -> single fp16
__global__ __launch_bounds__(256) void cvt_h1_kernel(
    const float* __restrict__ src, __half* __restrict__ dst, long n4)
{
    long i = (long)blockIdx.x * 256 + threadIdx.x;
    if (i >= n4) return;
    float4 v = ((const float4*)src)[i];
    ((__half2*)dst)[2*i]   = __halves2half2(__float2half_rn(v.x), __float2half_rn(v.y));
    ((__half2*)dst)[2*i+1] = __halves2half2(__float2half_rn(v.z), __float2half_rn(v.w));
}

// fp32 -> double fp16 (value + residual); rows >= rows_src zeroed (padding)
__global__ __launch_bounds__(256) void cvt_h2_pad_kernel(
    const float* __restrict__ src, __half* __restrict__ d1, __half* __restrict__ d2,
    long n4, long rows_src, long cols4)
{
    long i = (long)blockIdx.x * 256 + threadIdx.x;
    if (i >= n4) return;
    float4 v = make_float4(0.f, 0.f, 0.f, 0.f);
    if (i / cols4 < rows_src) v = ((const float4*)src)[i];
    __half h0 = __float2half_rn(v.x), h1 = __float2half_rn(v.y);
    __half h2 = __float2half_rn(v.z), h3 = __float2half_rn(v.w);
    __half r0 = __float2half_rn(v.x - __half2float(h0));
    __half r1 = __float2half_rn(v.y - __half2float(h1));
    __half r2 = __float2half_rn(v.z - __half2float(h2));
    __half r3 = __float2half_rn(v.w - __half2float(h3));
    ((__half2*)d1)[2*i]   = __halves2half2(h0, h1);
    ((__half2*)d1)[2*i+1] = __halves2half2(h2, h3);
    ((__half2*)d2)[2*i]   = __halves2half2(r0, r1);
    ((__half2*)d2)[2*i+1] = __halves2half2(r2, r3);
}

// ================= fp16 2-pass NT GEMM =================
// C[m][n] = sum_k a1[m][k]*(b1[n][k] + b2[n][k]);  single fp32 accumulator.
// CTA tile 128x128, K-step 32, 3-stage cp.async (race-free), 8 warps (2M x 4N).
#define FSTAGES 3
#define FROWH 40                              // halfs per row (80 B, conflict-free)
#define FTILE (128 * FROWH)                   // halfs per tile
#define FSTAGE (3 * FTILE)                    // A1, B1, B2
#define FGEMM_SMEM (FSTAGES * FSTAGE * 2)     // 92160 bytes

__global__ __launch_bounds__(256, 1) void gemm_f16(
    const __half* __restrict__ A1,
    const __half* __restrict__ B1, const __half* __restrict__ B2,
    float* __restrict__ C, int Ktot, int ldc)
{
    extern __shared__ __half fsm[];
    const int tid = threadIdx.x;
    const int wid = tid >> 5;
    const int lane = tid & 31;

    const int m0 = blockIdx.y * 128;
    const int n0 = blockIdx.x * 128;

    const int lrow = tid >> 2;           // 0..63 (each tile row = 64B = 4 chunks)
    const int lch  = (tid & 3) * 8;      // half-offset of 16B chunk

    const __half* a1p = A1 + (size_t)m0 * Ktot;
    const __half* b1p = B1 + (size_t)n0 * Ktot;
    const __half* b2p = B2 + (size_t)n0 * Ktot;

    auto load_stage = [&](int s, int k0) {
        __half* st = fsm + s * FSTAGE;
#pragma unroll
        for (int q = 0; q < 2; q++) {
            int row = lrow + q * 64;
            uint32_t d = smem_u32(st + row * FROWH + lch);
            CPA16(d,                 a1p + (size_t)row * Ktot + k0 + lch);
            CPA16(d + FTILE * 2,     b1p + (size_t)row * Ktot + k0 + lch);
            CPA16(d + 2 * FTILE * 2, b2p + (size_t)row * Ktot + k0 + lch);
        }
        asm volatile("cp.async.commit_group;" ::: "memory");
    };

    // warp tiling: 2 warps along M (64 rows), 4 along N (32 cols)
    const int wm = (wid & 1) * 64;
    const int wn = (wid >> 1) * 32;
    const int fr = lane & 15;
    const int fch = (lane >> 4) * 8;     // half offset

    float acc[4][4][4];
#pragma unroll
    for (int a = 0; a < 4; a++)
#pragma unroll
        for (int b = 0; b < 4; b++)
#pragma unroll
            for (int c = 0; c < 4; c++) acc[a][b][c] = 0.f;

    const int KT = Ktot / 32;
    load_stage(0, 0);
    load_stage(1, 32);

    int cur = 0, nxt = 2;
    for (int kt = 0; kt < KT; kt++) {
        if (kt < KT - 1) {
            asm volatile("cp.async.wait_group 1;" ::: "memory");
        } else {
            asm volatile("cp.async.wait_group 0;" ::: "memory");
        }
        __syncthreads();
        if (kt + 2 < KT) load_stage(nxt, (kt + 2) * 32);   // buffer consumed at kt-1

        const __half* st = fsm + cur * FSTAGE;
#pragma unroll
        for (int kk = 0; kk < 2; kk++) {
            const int kof = kk * 16;
            uint32_t af[4][4];
#pragma unroll
            for (int mb = 0; mb < 4; mb++) {
                uint32_t adr = smem_u32(st + (wm + mb * 16 + fr) * FROWH + kof + fch);
                LDSM4(af[mb], adr);
            }
            uint32_t b1f[2][4], b2f[2][4];
#pragma unroll
            for (int nb2 = 0; nb2 < 2; nb2++) {
                uint32_t adr = smem_u32(st + FTILE + (wn + nb2 * 16 + fr) * FROWH + kof + fch);
                LDSM4(b1f[nb2], adr);
                LDSM4(b2f[nb2], adr + FTILE * 2);
            }
            // pass 1: a1 . b1
#pragma unroll
            for (int mb = 0; mb < 4; mb++)
#pragma unroll
                for (int nb = 0; nb < 4; nb++)
                    MMAF16(acc[mb][nb], af[mb], b1f[nb >> 1][nb & 1], b1f[nb >> 1][(nb & 1) + 2]);
            // pass 2: a1 . b2  (weight residual, same accumulator)
#pragma unroll
            for (int mb = 0; mb < 4; mb++)
#pragma unroll
                for (int nb = 0; nb < 4; nb++)
                    MMAF16(acc[mb][nb], af[mb], b2f[nb >> 1][nb & 1], b2f[nb >> 1][(nb & 1) + 2]);
        }
        cur = (cur == 2) ? 0 : cur + 1;
        nxt = (nxt == 2) ? 0 : nxt + 1;
    }

    const int er = lane >> 2;
    const int ec = (lane & 3) * 2;
#pragma unroll
    for (int mb = 0; mb < 4; mb++) {
#pragma unroll
        for (int nb = 0; nb < 4; nb++) {
            float* p0 = C + (size_t)(m0 + wm + mb * 16 + er) * ldc + n0 + wn + nb * 8 + ec;
            float* p1 = p0 + 8 * ldc;
            *(float2*)p0 = make_float2(acc[mb][nb][0], acc[mb][nb][1]);
            *(float2*)p1 = make_float2(acc[mb][nb][2], acc[mb][nb][3]);
        }
    }
}

// ---------------- fp32 NT SGEMM (kept for small per-chunk C@B^T) ----------------
__global__ __launch_bounds__(256) void sgemm_nt(
    const float* __restrict__ A, const float* __restrict__ Bm, float* __restrict__ C,
    int M, int N, int K, int lda, int ldb, int ldc,
    long sA, long sB, long sC)
{
    const float* Ab = A + (long)blockIdx.z * sA;
    const float* Bb = Bm + (long)blockIdx.z * sB;
    float* Cb = C + (long)blockIdx.z * sC;

    __shared__ float As[16][128];
    __shared__ float Bs[16][128];

    const int tid = threadIdx.x;
    const int m0 = blockIdx.y * 128;
    const int n0 = blockIdx.x * 128;
    const int tx = tid & 15;
    const int ty = tid >> 4;

    const int lrow = tid >> 1;
    const int lk = (tid & 1) * 8;
    const float* Aload = Ab + (long)(m0 + lrow) * lda + lk;
    const float* Bload = Bb + (long)(n0 + lrow) * ldb + lk;
    const bool bvalid = (n0 + lrow) < N;

    float acc[8][8];
#pragma unroll
    for (int i = 0; i < 8; i++)
#pragma unroll
        for (int j = 0; j < 8; j++) acc[i][j] = 0.0f;

    float4 a0 = *(const float4*)(Aload);
    float4 a1 = *(const float4*)(Aload + 4);
    float4 b0 = make_float4(0.f,0.f,0.f,0.f), b1 = make_float4(0.f,0.f,0.f,0.f);
    if (bvalid) { b0 = *(const float4*)(Bload); b1 = *(const float4*)(Bload + 4); }

    for (int k0 = 0; k0 < K; k0 += 16) {
        As[lk+0][lrow] = a0.x; As[lk+1][lrow] = a0.y; As[lk+2][lrow] = a0.z; As[lk+3][lrow] = a0.w;
        As[lk+4][lrow] = a1.x; As[lk+5][lrow] = a1.y; As[lk+6][lrow] = a1.z; As[lk+7][lrow] = a1.w;
        Bs[lk+0][lrow] = b0.x; Bs[lk+1][lrow] = b0.y; Bs[lk+2][lrow] = b0.z; Bs[lk+3][lrow] = b0.w;
        Bs[lk+4][lrow] = b1.x; Bs[lk+5][lrow] = b1.y; Bs[lk+6][lrow] = b1.z; Bs[lk+7][lrow] = b1.w;
        __syncthreads();
        if (k0 + 16 < K) {
            a0 = *(const float4*)(Aload + k0 + 16);
            a1 = *(const float4*)(Aload + k0 + 20);
            if (bvalid) {
                b0 = *(const float4*)(Bload + k0 + 16);
                b1 = *(const float4*)(Bload + k0 + 20);
            }
        }
#pragma unroll
        for (int kk = 0; kk < 16; kk++) {
            float av[8], bv[8];
            *(float4*)&av[0] = *(const float4*)&As[kk][ty*8];
            *(float4*)&av[4] = *(const float4*)&As[kk][ty*8+4];
            *(float4*)&bv[0] = *(const float4*)&Bs[kk][tx*8];
            *(float4*)&bv[4] = *(const float4*)&Bs[kk][tx*8+4];
#pragma unroll
            for (int i = 0; i < 8; i++)
#pragma unroll
                for (int j = 0; j < 8; j++) acc[i][j] += av[i]*bv[j];
        }
        __syncthreads();
    }

#pragma unroll
    for (int i = 0; i < 8; i++) {
        int row = m0 + ty*8 + i;
        float* Crow = Cb + (long)row*ldc + n0 + tx*8;
        if (n0 + tx*8 + 4 <= N) {
            *(float4*)Crow = make_float4(acc[i][0],acc[i][1],acc[i][2],acc[i][3]);
        }
        if (n0 + tx*8 + 8 <= N) {
            *(float4*)(Crow+4) = make_float4(acc[i][4],acc[i][5],acc[i][6],acc[i][7]);
        }
    }
}

// ---------------- causal depthwise conv (width 4) + SiLU ----------------
__global__ void conv_silu_kernel(const float* __restrict__ conv_w,
                                 const float* __restrict__ conv_b)
{
    int cc = blockIdx.x * 256 + threadIdx.x;
    int r = blockIdx.y;
    int l = r & (L_ - 1);
    float acc = conv_b[cc];
    const float* col = g_zx + (size_t)r * DPJA + DI + cc;
#pragma unroll
    for (int w = 0; w < 4; w++) {
        int lp = l - 3 + w;
        if (lp >= 0) acc += col[(long)(w - 3) * DPJA] * conv_w[cc*4 + w];
    }
    float s = acc / (1.0f + __expf(-acc));
    g_xBC[(size_t)r * CD + cc] = s;
}

// ---------------- dt softplus + within-chunk cumsum of dt*A (parallel scan) ----------------
__global__ __launch_bounds__(256) void dt_cumsum_kernel(const float* __restrict__ dt_bias,
                                                        const float* __restrict__ A_log)
{
    __shared__ float wsum[8];
    const int chunk = blockIdx.x;
    const int h = blockIdx.y;
    const int i = threadIdx.x;
    const int lane = i & 31, wid = i >> 5;
    const int r = chunk * CK + i;

    float Ahd = -expf(A_log[h]);
    float x = g_zx[(size_t)r * DPJA + DI + CD + h] + dt_bias[h];
    float dt = fmaxf(x, 0.f) + log1pf(expf(-fabsf(x)));
    g_dt[r*NH + h] = dt;

    float v = dt * Ahd;
#pragma unroll
    for (int o = 1; o < 32; o <<= 1) {
        float n = __shfl_up_sync(0xffffffffu, v, o);
        if (lane >= o) v += n;
    }
    if (lane == 31) wsum[wid] = v;
    __syncthreads();
    float add = 0.f;
#pragma unroll
    for (int wq = 0; wq < 8; wq++) {
        float ws = wsum[wq];
        add += (wq < wid) ? ws : 0.f;
    }
    g_dacs[r*NH + h] = v + add;
}

// ---------------- per-(chunk,head) state accumulation ----------------
__global__ __launch_bounds__(256) void states_kernel()
{
    int chunk = blockIdx.x;
    int h = blockIdx.y;
    int base = chunk * CK;
    int tid = threadIdx.x;

    __shared__ float ws[CK];
    __shared__ float xs[32*64];
    __shared__ float Bsh[32*128];

    {
        float dl = g_dacs[(base + CK - 1)*NH + h];
        float dv = g_dacs[(base + tid)*NH + h];
        ws[tid] = __expf(dl - dv) * g_dt[(base + tid)*NH + h];
    }

    const int tp = tid >> 5;
    const int tn = tid & 31;
    float acc[8][4];
#pragma unroll
    for (int a = 0; a < 8; a++)
#pragma unroll
        for (int b = 0; b < 4; b++) acc[a][b] = 0.f;

    for (int st = 0; st < 8; st++) {
        __syncthreads();
#pragma unroll
        for (int rep = 0; rep < 2; rep++) {
            int f = tid + rep*256;
            int row = f >> 4, c4 = f & 15;
            *(float4*)&xs[row*64 + c4*4] =
                *(const float4*)&g_xBC[(size_t)(base + st*32 + row)*CD + h*64 + c4*4];
        }
#pragma unroll
        for (int rep = 0; rep < 4; rep++) {
            int f = tid + rep*256;
            int row = f >> 5, c4 = f & 31;
            *(float4*)&Bsh[row*128 + c4*4] =
                *(const float4*)&g_xBC[(size_t)(base + st*32 + row)*CD + DI + c4*4];
        }
        __syncthreads();

        for (int s = 0; s < 32; s++) {
            float w = ws[st*32 + s];
            float4 bv = *(const float4*)&Bsh[s*128 + tn*4];
            float xw[8];
#pragma unroll
            for (int pp = 0; pp < 8; pp++) xw[pp] = w * xs[s*64 + tp + pp*8];
#pragma unroll
            for (int pp = 0; pp < 8; pp++) {
                acc[pp][0] += xw[pp]*bv.x;
                acc[pp][1] += xw[pp]*bv.y;
                acc[pp][2] += xw[pp]*bv.z;
                acc[pp][3] += xw[pp]*bv.w;
            }
        }
    }

    size_t obase = (size_t)(chunk*NH + h) * DH * NS;
#pragma unroll
    for (int pp = 0; pp < 8; pp++) {
        *(float4*)&g_states[obase + (size_t)(tp + pp*8)*NS + tn*4] =
            make_float4(acc[pp][0], acc[pp][1], acc[pp][2], acc[pp][3]);
    }
}

// ---------------- inter-chunk scan ----------------
__global__ void scan_kernel()
{
    int idx = blockIdx.x * 256 + threadIdx.x;
    int h = (idx >> 13) & 63;
    int b = idx >> 19;
    float s = 0.f;
    for (int c = 0; c < 16; c++) {
        size_t off = ((size_t)(b*16 + c)*NH + h)*DH*NS + (idx & 8191);
        g_prev[off] = s;
        float dec = __expf(g_dacs[(size_t)(b*L_ + c*CK + CK - 1)*NH + h]);
        s = s * dec + g_states[off];
    }
}

// ---------------- fused y = y_diag + y_off + Dp*x per (chunk, head) ----------------
#define Y_SMEM_BYTES ((256*64 + 128*68 + 256*36 + 256 + 256) * 4)
__global__ __launch_bounds__(256) void y_kernel(const float* __restrict__ Dp)
{
    extern __shared__ float sm[];
    float* xs    = sm;
    float* prevT = xs + 256*64;
    float* Cs    = prevT + 128*68;
    float* das   = Cs + 256*36;
    float* dts   = das + 256;

    int chunk = blockIdx.x;
    int h = blockIdx.y;
    int base = chunk * CK;
    int tid = threadIdx.x;

    int w = tid >> 5, lane = tid & 31;
    int rb = (w < 4) ? (2*w) : (7 - 2*(w - 4));
    int i = rb*32 + lane;

    {
        const float4* src = (const float4*)&g_xBC[(size_t)(base + i)*CD + h*64];
        float4* dst = (float4*)&xs[i*64];
#pragma unroll
        for (int q = 0; q < 16; q++) dst[q] = src[q];
    }
    das[i] = g_dacs[(base + i)*NH + h];
    dts[i] = g_dt[(base + i)*NH + h];
    {
        size_t pb = (size_t)(chunk*NH + h) * DH * NS;
#pragma unroll
        for (int e = 0; e < 32; e++) {
            int f = tid + e*256;
            int p = f >> 7, n = f & 127;
            prevT[n*68 + p] = g_prev[pb + f];
        }
    }
    __syncthreads();

    float dai = das[i];
    float dph = Dp[h];
    float acc[64];
    {
        const float4* xr = (const float4*)&xs[i*64];
#pragma unroll
        for (int q = 0; q < 16; q++) {
            float4 v = xr[q];
            acc[4*q+0] = dph*v.x; acc[4*q+1] = dph*v.y;
            acc[4*q+2] = dph*v.z; acc[4*q+3] = dph*v.w;
        }
    }

    const float* cb = g_CBt + (size_t)chunk * CK * CK;
    for (int j = 0; j <= i; j++) {
        float wgt = cb[j*CK + i] * __expf(dai - das[j]) * dts[j];
        const float4* xr = (const float4*)&xs[j*64];
#pragma unroll
        for (int q = 0; q < 16; q++) {
            float4 v = xr[q];
            acc[4*q+0] += wgt*v.x; acc[4*q+1] += wgt*v.y;
            acc[4*q+2] += wgt*v.z; acc[4*q+3] += wgt*v.w;
        }
    }

    float ei = __expf(dai);
    for (int nt = 0; nt < 4; nt++) {
        {
            const float4* src = (const float4*)&g_xBC[(size_t)(base + i)*CD + DI + NS + nt*32];
            float4* dst = (float4*)&Cs[i*36];
#pragma unroll
            for (int q = 0; q < 8; q++) dst[q] = src[q];
        }
        __syncthreads();
        for (int nn = 0; nn < 32; nn++) {
            float cv = ei * Cs[i*36 + nn];
            const float4* pr = (const float4*)&prevT[(nt*32 + nn)*68];
#pragma unroll
            for (int q = 0; q < 16; q++) {
                float4 v = pr[q];
                acc[4*q+0] += cv*v.x; acc[4*q+1] += cv*v.y;
                acc[4*q+2] += cv*v.z; acc[4*q+3] += cv*v.w;
            }
        }
        __syncthreads();
    }

    {
        float4* dst = (float4*)&g_y[(size_t)(base + i)*DI + h*64];
#pragma unroll
        for (int q = 0; q < 16; q++)
            dst[q] = make_float4(acc[4*q], acc[4*q+1], acc[4*q+2], acc[4*q+3]);
    }
}

// ---------------- gate (silu(z)) + RMSNorm ----------------
__global__ __launch_bounds__(256) void gate_norm_kernel(const float* __restrict__ norm_w)
{
    __shared__ float buf[DI];
    __shared__ float red[8];
    int r = blockIdx.x;
    int tid = threadIdx.x;
    float ss = 0.f;
#pragma unroll
    for (int e = 0; e < 16; e++) {
        int c = tid + e*256;
        float y = g_y[(size_t)r*DI + c];
        float z = g_zx[(size_t)r*DPJA + c];
        float g = y * (z / (1.f + __expf(-z)));
        buf[c] = g;
        ss += g*g;
    }
#pragma unroll
    for (int o = 16; o > 0; o >>= 1) ss += __shfl_xor_sync(0xffffffffu, ss, o);
    if ((tid & 31) == 0) red[tid >> 5] = ss;
    __syncthreads();
    float tot = 0.f;
#pragma unroll
    for (int q = 0; q < 8; q++) tot += red[q];
    float scale = rsqrtf(tot / (float)DI + 1e-5f);
#pragma unroll
    for (int e = 0; e < 16; e++) {
        int c = tid + e*256;
        g_y[(size_t)r*DI + c] = buf[c] * scale * norm_w[c];
    }
}

// ---------------- launch ----------------
extern "C" void kernel_launch(void* const* d_in, const int* in_sizes, int n_in,
                              void* d_out, int out_size)
{
    const float* u       = (const float*)d_in[0];
    const float* W_in    = (const float*)d_in[1];
    const float* conv_w  = (const float*)d_in[2];
    const float* conv_b  = (const float*)d_in[3];
    const float* dt_bias = (const float*)d_in[4];
    const float* A_log   = (const float*)d_in[5];
    const float* Dp      = (const float*)d_in[6];
    const float* norm_w  = (const float*)d_in[7];
    const float* W_out   = (const float*)d_in[8];
    float* out = (float*)d_out;

    float *zx, *xbc, *cbt, *y;
    __half *uh, *wi1, *wi2, *yh, *wo1, *wo2;
    cudaGetSymbolAddress((void**)&zx,  g_zx);
    cudaGetSymbolAddress((void**)&xbc, g_xBC);
    cudaGetSymbolAddress((void**)&cbt, g_CBt);
    cudaGetSymbolAddress((void**)&y,   g_y);
    cudaGetSymbolAddress((void**)&uh,  g_uh);
    cudaGetSymbolAddress((void**)&wi1, g_wi1);
    cudaGetSymbolAddress((void**)&wi2, g_wi2);
    cudaGetSymbolAddress((void**)&yh,  g_yh);
    cudaGetSymbolAddress((void**)&wo1, g_wo1);
    cudaGetSymbolAddress((void**)&wo2, g_wo2);

    cudaFuncSetAttribute(y_kernel, cudaFuncAttributeMaxDynamicSharedMemorySize, Y_SMEM_BYTES);
    cudaFuncSetAttribute(gemm_f16, cudaFuncAttributeMaxDynamicSharedMemorySize, FGEMM_SMEM);

    // convert inputs for GEMM1 (activations: 1x fp16; weights: 2x fp16)
    {
        long n4 = (long)RW * DM / 4;
        cvt_h1_kernel<<<(int)((n4 + 255) / 256), 256>>>(u, uh, n4);
    }
    {
        long n4 = (long)DPJA * DM / 4;
        cvt_h2_pad_kernel<<<(int)((n4 + 255) / 256), 256>>>(W_in, wi1, wi2, n4, DPJ, DM/4);
    }

    // 1) in-proj: zx[8192, 8704(pad)] = u @ W_in^T  (fp16 2-pass)
    gemm_f16<<<dim3(DPJA/128, RW/128), 256, FGEMM_SMEM>>>(uh, wi1, wi2, zx, DM, DPJA);

    // 2) conv + silu
    conv_silu_kernel<<<dim3(CD/256, RW), 256>>>(conv_w, conv_b);

    // 3) dt softplus + per-chunk cumsum (parallel scan)
    dt_cumsum_kernel<<<dim3(NCH, NH), 256>>>(dt_bias, A_log);

    // 4) per-chunk CBt
    dim3 g2(2, 2, NCH);
    sgemm_nt<<<g2, 256>>>(xbc + DI, xbc + DI + NS, cbt,
                          CK, CK, NS, CD, CD, CK,
                          (long)CK*CD, (long)CK*CD, (long)CK*CK);

    // 5) states
    states_kernel<<<dim3(NCH, NH), 256>>>();

    // 6) inter-chunk scan
    scan_kernel<<<4096, 256>>>();

    // 7) fused y
    y_kernel<<<dim3(NCH, NH), 256, Y_SMEM_BYTES>>>(Dp);

    // 8) gate + RMSNorm
    gate_norm_kernel<<<RW, 256>>>(norm_w);

    // convert for GEMM2
    {
        long n4 = (long)RW * DI / 4;
        cvt_h1_kernel<<<(int)((n4 + 255) / 256), 256>>>(y, yh, n4);
    }
    {
        long n4 = (long)DM * DI / 4;
        cvt_h2_pad_kernel<<<(int)((n4 + 255) / 256), 256>>>(W_out, wo1, wo2, n4, DM, DI/4);
    }

    // 9) out-proj: out[8192,2048] = y @ W_out^T  (fp16 2-pass)
    gemm_f16<<<dim3(DM/128, RW/128), 256, FGEMM_SMEM>>>(yh, wo1, wo2, out, DI, DM);
}

// round 9
// speedup vs baseline: 3.2763x; 1.3548x over previous
#include <cuda_runtime.h>
#include <cuda_fp16.h>
#include <math.h>
#include <stdint.h>

// ---------------- problem constants ----------------
#define L_   4096
#define DM   2048          // D_MODEL
#define DI   4096          // D_INNER
#define NH   64            // N_HEADS
#define DH   64            // D_HEAD
#define NS   128           // D_STATE
#define CD   4352          // CONV_DIM
#define DPJ  8512          // D_IN_PROJ
#define DPJA 8704          // padded to 68*128 for GEMM tiles
#define CK   256           // CHUNK
#define NCH  32            // total chunks
#define RW   8192          // total rows = B*L

// ---------------- scratch (device globals; no allocations) ----------------
__device__ float g_zx[(size_t)RW * DPJA];
__device__ float g_xBC[(size_t)RW * CD];
__device__ float g_dt[RW * NH];
__device__ float g_dacs[RW * NH];
__device__ float g_CBt[NCH * CK * CK];
__device__ float g_states[(size_t)NCH * NH * DH * NS];
__device__ float g_prev[(size_t)NCH * NH * DH * NS];
__device__ float g_y[(size_t)RW * DI];
// fp16 operands (single precision-level, 1-pass GEMMs)
__device__ __half g_uh[(size_t)RW * DM];
__device__ __half g_wi1[(size_t)DPJA * DM];
__device__ __half g_yh[(size_t)RW * DI];
__device__ __half g_wo1[(size_t)DM * DI];

// ================= PTX helpers (portable, compute_103-safe) =================
__device__ __forceinline__ uint32_t smem_u32(const void* p) {
    uint32_t a;
    asm("{ .reg .u64 t; cvta.to.shared.u64 t, %1; cvt.u32.u64 %0, t; }" : "=r"(a) : "l"(p));
    return a;
}
#define CPA16(dst, src) \
    asm volatile("cp.async.cg.shared.global [%0], [%1], 16;" :: "r"(dst), "l"(src) : "memory")

#define LDSM4(r, adr)                                                            \
    asm volatile("ldmatrix.sync.aligned.m8n8.x4.shared.b16 {%0,%1,%2,%3}, [%4];" \
        : "=r"((r)[0]), "=r"((r)[1]), "=r"((r)[2]), "=r"((r)[3]) : "r"(adr))

#define MMAF16(c, a, b0, b1)                                                     \
    asm volatile("mma.sync.aligned.m16n8k16.row.col.f32.f16.f16.f32 "            \
        "{%0,%1,%2,%3}, {%4,%5,%6,%7}, {%8,%9}, {%0,%1,%2,%3};"                  \
        : "+f"((c)[0]), "+f"((c)[1]), "+f"((c)[2]), "+f"((c)[3])                  \
        : "r"((a)[0]), "r"((a)[1]), "r"((a)[2]), "r"((a)[3]), "r"(b0), "r"(b1))

// ================= conversion kernels =================
// fp32 -> fp16
__global__ __launch_bounds__(256) void cvt_h1_kernel(
    const float* __restrict__ src, __half* __restrict__ dst, long n4)
{
    long i = (long)blockIdx.x * 256 + threadIdx.x;
    if (i >= n4) return;
    float4 v = ((const float4*)src)[i];
    ((__half2*)dst)[2*i]   = __halves2half2(__float2half_rn(v.x), __float2half_rn(v.y));
    ((__half2*)dst)[2*i+1] = __halves2half2(__float2half_rn(v.z), __float2half_rn(v.w));
}

// fp32 -> fp16 with zero-padded rows beyond rows_src
__global__ __launch_bounds__(256) void cvt_h1_pad_kernel(
    const float* __restrict__ src, __half* __restrict__ dst,
    long n4, long rows_src, long cols4)
{
    long i = (long)blockIdx.x * 256 + threadIdx.x;
    if (i >= n4) return;
    float4 v = make_float4(0.f, 0.f, 0.f, 0.f);
    if (i / cols4 < rows_src) v = ((const float4*)src)[i];
    ((__half2*)dst)[2*i]   = __halves2half2(__float2half_rn(v.x), __float2half_rn(v.y));
    ((__half2*)dst)[2*i+1] = __halves2half2(__float2half_rn(v.z), __float2half_rn(v.w));
}

// ================= fp16 1-pass NT GEMM =================
// C[m][n] = sum_k A[m][k]*B[n][k]; fp32 accumulate.
// CTA tile 128x128, K-step 32, 3-stage cp.async (race-free), 8 warps (2M x 4N).
#define FSTAGES 3
#define FROWH 40                              // halfs per row (80 B, conflict-free)
#define FTILE (128 * FROWH)                   // halfs per tile
#define FSTAGE (2 * FTILE)                    // A, B
#define FGEMM_SMEM (FSTAGES * FSTAGE * 2)     // 61440 bytes

__global__ __launch_bounds__(256, 1) void gemm_f16(
    const __half* __restrict__ A1, const __half* __restrict__ B1,
    float* __restrict__ C, int Ktot, int ldc)
{
    extern __shared__ __half fsm[];
    const int tid = threadIdx.x;
    const int wid = tid >> 5;
    const int lane = tid & 31;

    const int m0 = blockIdx.y * 128;
    const int n0 = blockIdx.x * 128;

    const int lrow = tid >> 2;           // 0..63
    const int lch  = (tid & 3) * 8;      // half-offset of 16B chunk

    const __half* a1p = A1 + (size_t)m0 * Ktot;
    const __half* b1p = B1 + (size_t)n0 * Ktot;

    auto load_stage = [&](int s, int k0) {
        __half* st = fsm + s * FSTAGE;
#pragma unroll
        for (int q = 0; q < 2; q++) {
            int row = lrow + q * 64;
            uint32_t d = smem_u32(st + row * FROWH + lch);
            CPA16(d,             a1p + (size_t)row * Ktot + k0 + lch);
            CPA16(d + FTILE * 2, b1p + (size_t)row * Ktot + k0 + lch);
        }
        asm volatile("cp.async.commit_group;" ::: "memory");
    };

    // warp tiling: 2 warps along M (64 rows), 4 along N (32 cols)
    const int wm = (wid & 1) * 64;
    const int wn = (wid >> 1) * 32;
    const int fr = lane & 15;
    const int fch = (lane >> 4) * 8;

    float acc[4][4][4];
#pragma unroll
    for (int a = 0; a < 4; a++)
#pragma unroll
        for (int b = 0; b < 4; b++)
#pragma unroll
            for (int c = 0; c < 4; c++) acc[a][b][c] = 0.f;

    const int KT = Ktot / 32;
    load_stage(0, 0);
    load_stage(1, 32);

    int cur = 0, nxt = 2;
    for (int kt = 0; kt < KT; kt++) {
        if (kt < KT - 1) {
            asm volatile("cp.async.wait_group 1;" ::: "memory");
        } else {
            asm volatile("cp.async.wait_group 0;" ::: "memory");
        }
        __syncthreads();
        if (kt + 2 < KT) load_stage(nxt, (kt + 2) * 32);   // buffer consumed at kt-1

        const __half* st = fsm + cur * FSTAGE;
#pragma unroll
        for (int kk = 0; kk < 2; kk++) {
            const int kof = kk * 16;
            uint32_t af[4][4];
#pragma unroll
            for (int mb = 0; mb < 4; mb++) {
                uint32_t adr = smem_u32(st + (wm + mb * 16 + fr) * FROWH + kof + fch);
                LDSM4(af[mb], adr);
            }
            uint32_t bf[2][4];
#pragma unroll
            for (int nb2 = 0; nb2 < 2; nb2++) {
                uint32_t adr = smem_u32(st + FTILE + (wn + nb2 * 16 + fr) * FROWH + kof + fch);
                LDSM4(bf[nb2], adr);
            }
#pragma unroll
            for (int mb = 0; mb < 4; mb++)
#pragma unroll
                for (int nb = 0; nb < 4; nb++)
                    MMAF16(acc[mb][nb], af[mb], bf[nb >> 1][nb & 1], bf[nb >> 1][(nb & 1) + 2]);
        }
        cur = (cur == 2) ? 0 : cur + 1;
        nxt = (nxt == 2) ? 0 : nxt + 1;
    }

    const int er = lane >> 2;
    const int ec = (lane & 3) * 2;
#pragma unroll
    for (int mb = 0; mb < 4; mb++) {
#pragma unroll
        for (int nb = 0; nb < 4; nb++) {
            float* p0 = C + (size_t)(m0 + wm + mb * 16 + er) * ldc + n0 + wn + nb * 8 + ec;
            float* p1 = p0 + 8 * ldc;
            *(float2*)p0 = make_float2(acc[mb][nb][0], acc[mb][nb][1]);
            *(float2*)p1 = make_float2(acc[mb][nb][2], acc[mb][nb][3]);
        }
    }
}

// ---------------- fp32 NT SGEMM (kept for small per-chunk C@B^T) ----------------
__global__ __launch_bounds__(256) void sgemm_nt(
    const float* __restrict__ A, const float* __restrict__ Bm, float* __restrict__ C,
    int M, int N, int K, int lda, int ldb, int ldc,
    long sA, long sB, long sC)
{
    const float* Ab = A + (long)blockIdx.z * sA;
    const float* Bb = Bm + (long)blockIdx.z * sB;
    float* Cb = C + (long)blockIdx.z * sC;

    __shared__ float As[16][128];
    __shared__ float Bs[16][128];

    const int tid = threadIdx.x;
    const int m0 = blockIdx.y * 128;
    const int n0 = blockIdx.x * 128;
    const int tx = tid & 15;
    const int ty = tid >> 4;

    const int lrow = tid >> 1;
    const int lk = (tid & 1) * 8;
    const float* Aload = Ab + (long)(m0 + lrow) * lda + lk;
    const float* Bload = Bb + (long)(n0 + lrow) * ldb + lk;
    const bool bvalid = (n0 + lrow) < N;

    float acc[8][8];
#pragma unroll
    for (int i = 0; i < 8; i++)
#pragma unroll
        for (int j = 0; j < 8; j++) acc[i][j] = 0.0f;

    float4 a0 = *(const float4*)(Aload);
    float4 a1 = *(const float4*)(Aload + 4);
    float4 b0 = make_float4(0.f,0.f,0.f,0.f), b1 = make_float4(0.f,0.f,0.f,0.f);
    if (bvalid) { b0 = *(const float4*)(Bload); b1 = *(const float4*)(Bload + 4); }

    for (int k0 = 0; k0 < K; k0 += 16) {
        As[lk+0][lrow] = a0.x; As[lk+1][lrow] = a0.y; As[lk+2][lrow] = a0.z; As[lk+3][lrow] = a0.w;
        As[lk+4][lrow] = a1.x; As[lk+5][lrow] = a1.y; As[lk+6][lrow] = a1.z; As[lk+7][lrow] = a1.w;
        Bs[lk+0][lrow] = b0.x; Bs[lk+1][lrow] = b0.y; Bs[lk+2][lrow] = b0.z; Bs[lk+3][lrow] = b0.w;
        Bs[lk+4][lrow] = b1.x; Bs[lk+5][lrow] = b1.y; Bs[lk+6][lrow] = b1.z; Bs[lk+7][lrow] = b1.w;
        __syncthreads();
        if (k0 + 16 < K) {
            a0 = *(const float4*)(Aload + k0 + 16);
            a1 = *(const float4*)(Aload + k0 + 20);
            if (bvalid) {
                b0 = *(const float4*)(Bload + k0 + 16);
                b1 = *(const float4*)(Bload + k0 + 20);
            }
        }
#pragma unroll
        for (int kk = 0; kk < 16; kk++) {
            float av[8], bv[8];
            *(float4*)&av[0] = *(const float4*)&As[kk][ty*8];
            *(float4*)&av[4] = *(const float4*)&As[kk][ty*8+4];
            *(float4*)&bv[0] = *(const float4*)&Bs[kk][tx*8];
            *(float4*)&bv[4] = *(const float4*)&Bs[kk][tx*8+4];
#pragma unroll
            for (int i = 0; i < 8; i++)
#pragma unroll
                for (int j = 0; j < 8; j++) acc[i][j] += av[i]*bv[j];
        }
        __syncthreads();
    }

#pragma unroll
    for (int i = 0; i < 8; i++) {
        int row = m0 + ty*8 + i;
        float* Crow = Cb + (long)row*ldc + n0 + tx*8;
        if (n0 + tx*8 + 4 <= N) {
            *(float4*)Crow = make_float4(acc[i][0],acc[i][1],acc[i][2],acc[i][3]);
        }
        if (n0 + tx*8 + 8 <= N) {
            *(float4*)(Crow+4) = make_float4(acc[i][4],acc[i][5],acc[i][6],acc[i][7]);
        }
    }
}

// ---------------- causal depthwise conv (width 4) + SiLU ----------------
__global__ void conv_silu_kernel(const float* __restrict__ conv_w,
                                 const float* __restrict__ conv_b)
{
    int cc = blockIdx.x * 256 + threadIdx.x;
    int r = blockIdx.y;
    int l = r & (L_ - 1);
    float acc = conv_b[cc];
    const float* col = g_zx + (size_t)r * DPJA + DI + cc;
#pragma unroll
    for (int w = 0; w < 4; w++) {
        int lp = l - 3 + w;
        if (lp >= 0) acc += col[(long)(w - 3) * DPJA] * conv_w[cc*4 + w];
    }
    float s = acc / (1.0f + __expf(-acc));
    g_xBC[(size_t)r * CD + cc] = s;
}

// ---------------- dt softplus + within-chunk cumsum of dt*A (parallel scan) ----------------
__global__ __launch_bounds__(256) void dt_cumsum_kernel(const float* __restrict__ dt_bias,
                                                        const float* __restrict__ A_log)
{
    __shared__ float wsum[8];
    const int chunk = blockIdx.x;
    const int h = blockIdx.y;
    const int i = threadIdx.x;
    const int lane = i & 31, wid = i >> 5;
    const int r = chunk * CK + i;

    float Ahd = -expf(A_log[h]);
    float x = g_zx[(size_t)r * DPJA + DI + CD + h] + dt_bias[h];
    float dt = fmaxf(x, 0.f) + log1pf(expf(-fabsf(x)));
    g_dt[r*NH + h] = dt;

    float v = dt * Ahd;
#pragma unroll
    for (int o = 1; o < 32; o <<= 1) {
        float n = __shfl_up_sync(0xffffffffu, v, o);
        if (lane >= o) v += n;
    }
    if (lane == 31) wsum[wid] = v;
    __syncthreads();
    float add = 0.f;
#pragma unroll
    for (int wq = 0; wq < 8; wq++) {
        float ws = wsum[wq];
        add += (wq < wid) ? ws : 0.f;
    }
    g_dacs[r*NH + h] = v + add;
}

// ---------------- per-(chunk,head) state accumulation ----------------
__global__ __launch_bounds__(256) void states_kernel()
{
    int chunk = blockIdx.x;
    int h = blockIdx.y;
    int base = chunk * CK;
    int tid = threadIdx.x;

    __shared__ float ws[CK];
    __shared__ float xs[32*64];
    __shared__ float Bsh[32*128];

    {
        float dl = g_dacs[(base + CK - 1)*NH + h];
        float dv = g_dacs[(base + tid)*NH + h];
        ws[tid] = __expf(dl - dv) * g_dt[(base + tid)*NH + h];
    }

    const int tp = tid >> 5;
    const int tn = tid & 31;
    float acc[8][4];
#pragma unroll
    for (int a = 0; a < 8; a++)
#pragma unroll
        for (int b = 0; b < 4; b++) acc[a][b] = 0.f;

    for (int st = 0; st < 8; st++) {
        __syncthreads();
#pragma unroll
        for (int rep = 0; rep < 2; rep++) {
            int f = tid + rep*256;
            int row = f >> 4, c4 = f & 15;
            *(float4*)&xs[row*64 + c4*4] =
                *(const float4*)&g_xBC[(size_t)(base + st*32 + row)*CD + h*64 + c4*4];
        }
#pragma unroll
        for (int rep = 0; rep < 4; rep++) {
            int f = tid + rep*256;
            int row = f >> 5, c4 = f & 31;
            *(float4*)&Bsh[row*128 + c4*4] =
                *(const float4*)&g_xBC[(size_t)(base + st*32 + row)*CD + DI + c4*4];
        }
        __syncthreads();

        for (int s = 0; s < 32; s++) {
            float w = ws[st*32 + s];
            float4 bv = *(const float4*)&Bsh[s*128 + tn*4];
            float xw[8];
#pragma unroll
            for (int pp = 0; pp < 8; pp++) xw[pp] = w * xs[s*64 + tp + pp*8];
#pragma unroll
            for (int pp = 0; pp < 8; pp++) {
                acc[pp][0] += xw[pp]*bv.x;
                acc[pp][1] += xw[pp]*bv.y;
                acc[pp][2] += xw[pp]*bv.z;
                acc[pp][3] += xw[pp]*bv.w;
            }
        }
    }

    size_t obase = (size_t)(chunk*NH + h) * DH * NS;
#pragma unroll
    for (int pp = 0; pp < 8; pp++) {
        *(float4*)&g_states[obase + (size_t)(tp + pp*8)*NS + tn*4] =
            make_float4(acc[pp][0], acc[pp][1], acc[pp][2], acc[pp][3]);
    }
}

// ---------------- inter-chunk scan ----------------
__global__ void scan_kernel()
{
    int idx = blockIdx.x * 256 + threadIdx.x;
    int h = (idx >> 13) & 63;
    int b = idx >> 19;
    float s = 0.f;
    for (int c = 0; c < 16; c++) {
        size_t off = ((size_t)(b*16 + c)*NH + h)*DH*NS + (idx & 8191);
        g_prev[off] = s;
        float dec = __expf(g_dacs[(size_t)(b*L_ + c*CK + CK - 1)*NH + h]);
        s = s * dec + g_states[off];
    }
}

// ---------------- fused y = y_diag + y_off + Dp*x per (chunk, head) ----------------
#define Y_SMEM_BYTES ((256*64 + 128*68 + 256*36 + 256 + 256) * 4)
__global__ __launch_bounds__(256) void y_kernel(const float* __restrict__ Dp)
{
    extern __shared__ float sm[];
    float* xs    = sm;
    float* prevT = xs + 256*64;
    float* Cs    = prevT + 128*68;
    float* das   = Cs + 256*36;
    float* dts   = das + 256;

    int chunk = blockIdx.x;
    int h = blockIdx.y;
    int base = chunk * CK;
    int tid = threadIdx.x;

    int w = tid >> 5, lane = tid & 31;
    int rb = (w < 4) ? (2*w) : (7 - 2*(w - 4));
    int i = rb*32 + lane;

    {
        const float4* src = (const float4*)&g_xBC[(size_t)(base + i)*CD + h*64];
        float4* dst = (float4*)&xs[i*64];
#pragma unroll
        for (int q = 0; q < 16; q++) dst[q] = src[q];
    }
    das[i] = g_dacs[(base + i)*NH + h];
    dts[i] = g_dt[(base + i)*NH + h];
    {
        size_t pb = (size_t)(chunk*NH + h) * DH * NS;
#pragma unroll
        for (int e = 0; e < 32; e++) {
            int f = tid + e*256;
            int p = f >> 7, n = f & 127;
            prevT[n*68 + p] = g_prev[pb + f];
        }
    }
    __syncthreads();

    float dai = das[i];
    float dph = Dp[h];
    float acc[64];
    {
        const float4* xr = (const float4*)&xs[i*64];
#pragma unroll
        for (int q = 0; q < 16; q++) {
            float4 v = xr[q];
            acc[4*q+0] = dph*v.x; acc[4*q+1] = dph*v.y;
            acc[4*q+2] = dph*v.z; acc[4*q+3] = dph*v.w;
        }
    }

    const float* cb = g_CBt + (size_t)chunk * CK * CK;
    for (int j = 0; j <= i; j++) {
        float wgt = cb[j*CK + i] * __expf(dai - das[j]) * dts[j];
        const float4* xr = (const float4*)&xs[j*64];
#pragma unroll
        for (int q = 0; q < 16; q++) {
            float4 v = xr[q];
            acc[4*q+0] += wgt*v.x; acc[4*q+1] += wgt*v.y;
            acc[4*q+2] += wgt*v.z; acc[4*q+3] += wgt*v.w;
        }
    }

    float ei = __expf(dai);
    for (int nt = 0; nt < 4; nt++) {
        {
            const float4* src = (const float4*)&g_xBC[(size_t)(base + i)*CD + DI + NS + nt*32];
            float4* dst = (float4*)&Cs[i*36];
#pragma unroll
            for (int q = 0; q < 8; q++) dst[q] = src[q];
        }
        __syncthreads();
        for (int nn = 0; nn < 32; nn++) {
            float cv = ei * Cs[i*36 + nn];
            const float4* pr = (const float4*)&prevT[(nt*32 + nn)*68];
#pragma unroll
            for (int q = 0; q < 16; q++) {
                float4 v = pr[q];
                acc[4*q+0] += cv*v.x; acc[4*q+1] += cv*v.y;
                acc[4*q+2] += cv*v.z; acc[4*q+3] += cv*v.w;
            }
        }
        __syncthreads();
    }

    {
        float4* dst = (float4*)&g_y[(size_t)(base + i)*DI + h*64];
#pragma unroll
        for (int q = 0; q < 16; q++)
            dst[q] = make_float4(acc[4*q], acc[4*q+1], acc[4*q+2], acc[4*q+3]);
    }
}

// ---------------- gate (silu(z)) + RMSNorm; writes fp16 operand directly ----------------
__global__ __launch_bounds__(256) void gate_norm_kernel(const float* __restrict__ norm_w)
{
    __shared__ float buf[DI];
    __shared__ float red[8];
    int r = blockIdx.x;
    int tid = threadIdx.x;
    float ss = 0.f;
#pragma unroll
    for (int e = 0; e < 16; e++) {
        int c = tid + e*256;
        float y = g_y[(size_t)r*DI + c];
        float z = g_zx[(size_t)r*DPJA + c];
        float g = y * (z / (1.f + __expf(-z)));
        buf[c] = g;
        ss += g*g;
    }
#pragma unroll
    for (int o = 16; o > 0; o >>= 1) ss += __shfl_xor_sync(0xffffffffu, ss, o);
    if ((tid & 31) == 0) red[tid >> 5] = ss;
    __syncthreads();
    float tot = 0.f;
#pragma unroll
    for (int q = 0; q < 8; q++) tot += red[q];
    float scale = rsqrtf(tot / (float)DI + 1e-5f);
#pragma unroll
    for (int e = 0; e < 16; e++) {
        int c = tid + e*256;
        g_yh[(size_t)r*DI + c] = __float2half_rn(buf[c] * scale * norm_w[c]);
    }
}

// ---------------- launch ----------------
extern "C" void kernel_launch(void* const* d_in, const int* in_sizes, int n_in,
                              void* d_out, int out_size)
{
    const float* u       = (const float*)d_in[0];
    const float* W_in    = (const float*)d_in[1];
    const float* conv_w  = (const float*)d_in[2];
    const float* conv_b  = (const float*)d_in[3];
    const float* dt_bias = (const float*)d_in[4];
    const float* A_log   = (const float*)d_in[5];
    const float* Dp      = (const float*)d_in[6];
    const float* norm_w  = (const float*)d_in[7];
    const float* W_out   = (const float*)d_in[8];
    float* out = (float*)d_out;

    float *zx, *xbc, *cbt;
    __half *uh, *wi1, *yh, *wo1;
    cudaGetSymbolAddress((void**)&zx,  g_zx);
    cudaGetSymbolAddress((void**)&xbc, g_xBC);
    cudaGetSymbolAddress((void**)&cbt, g_CBt);
    cudaGetSymbolAddress((void**)&uh,  g_uh);
    cudaGetSymbolAddress((void**)&wi1, g_wi1);
    cudaGetSymbolAddress((void**)&yh,  g_yh);
    cudaGetSymbolAddress((void**)&wo1, g_wo1);

    cudaFuncSetAttribute(y_kernel, cudaFuncAttributeMaxDynamicSharedMemorySize, Y_SMEM_BYTES);
    cudaFuncSetAttribute(gemm_f16, cudaFuncAttributeMaxDynamicSharedMemorySize, FGEMM_SMEM);

    // convert inputs for GEMM1
    {
        long n4 = (long)RW * DM / 4;
        cvt_h1_kernel<<<(int)((n4 + 255) / 256), 256>>>(u, uh, n4);
    }
    {
        long n4 = (long)DPJA * DM / 4;
        cvt_h1_pad_kernel<<<(int)((n4 + 255) / 256), 256>>>(W_in, wi1, n4, DPJ, DM/4);
    }

    // 1) in-proj: zx[8192, 8704(pad)] = u @ W_in^T  (fp16 1-pass)
    gemm_f16<<<dim3(DPJA/128, RW/128), 256, FGEMM_SMEM>>>(uh, wi1, zx, DM, DPJA);

    // 2) conv + silu
    conv_silu_kernel<<<dim3(CD/256, RW), 256>>>(conv_w, conv_b);

    // 3) dt softplus + per-chunk cumsum (parallel scan)
    dt_cumsum_kernel<<<dim3(NCH, NH), 256>>>(dt_bias, A_log);

    // 4) per-chunk CBt
    dim3 g2(2, 2, NCH);
    sgemm_nt<<<g2, 256>>>(xbc + DI, xbc + DI + NS, cbt,
                          CK, CK, NS, CD, CD, CK,
                          (long)CK*CD, (long)CK*CD, (long)CK*CK);

    // 5) states
    states_kernel<<<dim3(NCH, NH), 256>>>();

    // 6) inter-chunk scan
    scan_kernel<<<4096, 256>>>();

    // 7) fused y
    y_kernel<<<dim3(NCH, NH), 256, Y_SMEM_BYTES>>>(Dp);

    // 8) gate + RMSNorm (writes yh fp16 directly)
    gate_norm_kernel<<<RW, 256>>>(norm_w);

    // convert W_out for GEMM2
    {
        long n4 = (long)DM * DI / 4;
        cvt_h1_kernel<<<(int)((n4 + 255) / 256), 256>>>(W_out, wo1, n4);
    }

    // 9) out-proj: out[8192,2048] = y @ W_out^T  (fp16 1-pass)
    gemm_f16<<<dim3(DM/128, RW/128), 256, FGEMM_SMEM>>>(yh, wo1, out, DI, DM);
}

// round 10
// speedup vs baseline: 4.7269x; 1.4427x over previous
#include <cuda_runtime.h>
#include <cuda_fp16.h>
#include <math.h>
#include <stdint.h>

// ---------------- problem constants ----------------
#define L_   4096
#define DM   2048          // D_MODEL
#define DI   4096          // D_INNER
#define NH   64            // N_HEADS
#define DH   64            // D_HEAD
#define NS   128           // D_STATE
#define CD   4352          // CONV_DIM
#define DPJ  8512          // D_IN_PROJ
#define DPJA 8704          // padded to 68*128 for GEMM tiles
#define CK   256           // CHUNK
#define NCH  32            // total chunks
#define RW   8192          // total rows = B*L

// ---------------- scratch (device globals; no allocations) ----------------
__device__ float g_zx[(size_t)RW * DPJA];
__device__ float g_xBC[(size_t)RW * CD];
__device__ float g_dt[RW * NH];
__device__ float g_dacs[RW * NH];
__device__ float g_CBt[NCH * CK * CK];
__device__ float g_states[(size_t)NCH * NH * DH * NS];
__device__ float g_prev[(size_t)NCH * NH * DH * NS];
__device__ float g_y[(size_t)RW * DI];
// fp16 operands (single precision-level, 1-pass GEMMs)
__device__ __half g_uh[(size_t)RW * DM];
__device__ __half g_wi1[(size_t)DPJA * DM];
__device__ __half g_yh[(size_t)RW * DI];
__device__ __half g_wo1[(size_t)DM * DI];

// ================= PTX helpers (portable, compute_103-safe) =================
__device__ __forceinline__ uint32_t smem_u32(const void* p) {
    uint32_t a;
    asm("{ .reg .u64 t; cvta.to.shared.u64 t, %1; cvt.u32.u64 %0, t; }" : "=r"(a) : "l"(p));
    return a;
}
#define CPA16(dst, src) \
    asm volatile("cp.async.cg.shared.global [%0], [%1], 16;" :: "r"(dst), "l"(src) : "memory")

#define LDSM4(r, adr)                                                            \
    asm volatile("ldmatrix.sync.aligned.m8n8.x4.shared.b16 {%0,%1,%2,%3}, [%4];" \
        : "=r"((r)[0]), "=r"((r)[1]), "=r"((r)[2]), "=r"((r)[3]) : "r"(adr))

#define MMAF16(c, a, b0, b1)                                                     \
    asm volatile("mma.sync.aligned.m16n8k16.row.col.f32.f16.f16.f32 "            \
        "{%0,%1,%2,%3}, {%4,%5,%6,%7}, {%8,%9}, {%0,%1,%2,%3};"                  \
        : "+f"((c)[0]), "+f"((c)[1]), "+f"((c)[2]), "+f"((c)[3])                  \
        : "r"((a)[0]), "r"((a)[1]), "r"((a)[2]), "r"((a)[3]), "r"(b0), "r"(b1))

// ================= conversion kernels =================
__global__ __launch_bounds__(256) void cvt_h1_kernel(
    const float* __restrict__ src, __half* __restrict__ dst, long n4)
{
    long i = (long)blockIdx.x * 256 + threadIdx.x;
    if (i >= n4) return;
    float4 v = ((const float4*)src)[i];
    ((__half2*)dst)[2*i]   = __halves2half2(__float2half_rn(v.x), __float2half_rn(v.y));
    ((__half2*)dst)[2*i+1] = __halves2half2(__float2half_rn(v.z), __float2half_rn(v.w));
}

__global__ __launch_bounds__(256) void cvt_h1_pad_kernel(
    const float* __restrict__ src, __half* __restrict__ dst,
    long n4, long rows_src, long cols4)
{
    long i = (long)blockIdx.x * 256 + threadIdx.x;
    if (i >= n4) return;
    float4 v = make_float4(0.f, 0.f, 0.f, 0.f);
    if (i / cols4 < rows_src) v = ((const float4*)src)[i];
    ((__half2*)dst)[2*i]   = __halves2half2(__float2half_rn(v.x), __float2half_rn(v.y));
    ((__half2*)dst)[2*i+1] = __halves2half2(__float2half_rn(v.z), __float2half_rn(v.w));
}

// ================= fp16 1-pass NT GEMM (unchanged, at HMMA issue ceiling) =================
#define FSTAGES 3
#define FROWH 40
#define FTILE (128 * FROWH)
#define FSTAGE (2 * FTILE)
#define FGEMM_SMEM (FSTAGES * FSTAGE * 2)

__global__ __launch_bounds__(256, 1) void gemm_f16(
    const __half* __restrict__ A1, const __half* __restrict__ B1,
    float* __restrict__ C, int Ktot, int ldc)
{
    extern __shared__ __half fsm[];
    const int tid = threadIdx.x;
    const int wid = tid >> 5;
    const int lane = tid & 31;

    const int m0 = blockIdx.y * 128;
    const int n0 = blockIdx.x * 128;

    const int lrow = tid >> 2;
    const int lch  = (tid & 3) * 8;

    const __half* a1p = A1 + (size_t)m0 * Ktot;
    const __half* b1p = B1 + (size_t)n0 * Ktot;

    auto load_stage = [&](int s, int k0) {
        __half* st = fsm + s * FSTAGE;
#pragma unroll
        for (int q = 0; q < 2; q++) {
            int row = lrow + q * 64;
            uint32_t d = smem_u32(st + row * FROWH + lch);
            CPA16(d,             a1p + (size_t)row * Ktot + k0 + lch);
            CPA16(d + FTILE * 2, b1p + (size_t)row * Ktot + k0 + lch);
        }
        asm volatile("cp.async.commit_group;" ::: "memory");
    };

    const int wm = (wid & 1) * 64;
    const int wn = (wid >> 1) * 32;
    const int fr = lane & 15;
    const int fch = (lane >> 4) * 8;

    float acc[4][4][4];
#pragma unroll
    for (int a = 0; a < 4; a++)
#pragma unroll
        for (int b = 0; b < 4; b++)
#pragma unroll
            for (int c = 0; c < 4; c++) acc[a][b][c] = 0.f;

    const int KT = Ktot / 32;
    load_stage(0, 0);
    load_stage(1, 32);

    int cur = 0, nxt = 2;
    for (int kt = 0; kt < KT; kt++) {
        if (kt < KT - 1) {
            asm volatile("cp.async.wait_group 1;" ::: "memory");
        } else {
            asm volatile("cp.async.wait_group 0;" ::: "memory");
        }
        __syncthreads();
        if (kt + 2 < KT) load_stage(nxt, (kt + 2) * 32);

        const __half* st = fsm + cur * FSTAGE;
#pragma unroll
        for (int kk = 0; kk < 2; kk++) {
            const int kof = kk * 16;
            uint32_t af[4][4];
#pragma unroll
            for (int mb = 0; mb < 4; mb++) {
                uint32_t adr = smem_u32(st + (wm + mb * 16 + fr) * FROWH + kof + fch);
                LDSM4(af[mb], adr);
            }
            uint32_t bf[2][4];
#pragma unroll
            for (int nb2 = 0; nb2 < 2; nb2++) {
                uint32_t adr = smem_u32(st + FTILE + (wn + nb2 * 16 + fr) * FROWH + kof + fch);
                LDSM4(bf[nb2], adr);
            }
#pragma unroll
            for (int mb = 0; mb < 4; mb++)
#pragma unroll
                for (int nb = 0; nb < 4; nb++)
                    MMAF16(acc[mb][nb], af[mb], bf[nb >> 1][nb & 1], bf[nb >> 1][(nb & 1) + 2]);
        }
        cur = (cur == 2) ? 0 : cur + 1;
        nxt = (nxt == 2) ? 0 : nxt + 1;
    }

    const int er = lane >> 2;
    const int ec = (lane & 3) * 2;
#pragma unroll
    for (int mb = 0; mb < 4; mb++) {
#pragma unroll
        for (int nb = 0; nb < 4; nb++) {
            float* p0 = C + (size_t)(m0 + wm + mb * 16 + er) * ldc + n0 + wn + nb * 8 + ec;
            float* p1 = p0 + 8 * ldc;
            *(float2*)p0 = make_float2(acc[mb][nb][0], acc[mb][nb][1]);
            *(float2*)p1 = make_float2(acc[mb][nb][2], acc[mb][nb][3]);
        }
    }
}

// ---------------- fp32 NT SGEMM (per-chunk C@B^T) ----------------
__global__ __launch_bounds__(256) void sgemm_nt(
    const float* __restrict__ A, const float* __restrict__ Bm, float* __restrict__ C,
    int M, int N, int K, int lda, int ldb, int ldc,
    long sA, long sB, long sC)
{
    const float* Ab = A + (long)blockIdx.z * sA;
    const float* Bb = Bm + (long)blockIdx.z * sB;
    float* Cb = C + (long)blockIdx.z * sC;

    __shared__ float As[16][128];
    __shared__ float Bs[16][128];

    const int tid = threadIdx.x;
    const int m0 = blockIdx.y * 128;
    const int n0 = blockIdx.x * 128;
    const int tx = tid & 15;
    const int ty = tid >> 4;

    const int lrow = tid >> 1;
    const int lk = (tid & 1) * 8;
    const float* Aload = Ab + (long)(m0 + lrow) * lda + lk;
    const float* Bload = Bb + (long)(n0 + lrow) * ldb + lk;
    const bool bvalid = (n0 + lrow) < N;

    float acc[8][8];
#pragma unroll
    for (int i = 0; i < 8; i++)
#pragma unroll
        for (int j = 0; j < 8; j++) acc[i][j] = 0.0f;

    float4 a0 = *(const float4*)(Aload);
    float4 a1 = *(const float4*)(Aload + 4);
    float4 b0 = make_float4(0.f,0.f,0.f,0.f), b1 = make_float4(0.f,0.f,0.f,0.f);
    if (bvalid) { b0 = *(const float4*)(Bload); b1 = *(const float4*)(Bload + 4); }

    for (int k0 = 0; k0 < K; k0 += 16) {
        As[lk+0][lrow] = a0.x; As[lk+1][lrow] = a0.y; As[lk+2][lrow] = a0.z; As[lk+3][lrow] = a0.w;
        As[lk+4][lrow] = a1.x; As[lk+5][lrow] = a1.y; As[lk+6][lrow] = a1.z; As[lk+7][lrow] = a1.w;
        Bs[lk+0][lrow] = b0.x; Bs[lk+1][lrow] = b0.y; Bs[lk+2][lrow] = b0.z; Bs[lk+3][lrow] = b0.w;
        Bs[lk+4][lrow] = b1.x; Bs[lk+5][lrow] = b1.y; Bs[lk+6][lrow] = b1.z; Bs[lk+7][lrow] = b1.w;
        __syncthreads();
        if (k0 + 16 < K) {
            a0 = *(const float4*)(Aload + k0 + 16);
            a1 = *(const float4*)(Aload + k0 + 20);
            if (bvalid) {
                b0 = *(const float4*)(Bload + k0 + 16);
                b1 = *(const float4*)(Bload + k0 + 20);
            }
        }
#pragma unroll
        for (int kk = 0; kk < 16; kk++) {
            float av[8], bv[8];
            *(float4*)&av[0] = *(const float4*)&As[kk][ty*8];
            *(float4*)&av[4] = *(const float4*)&As[kk][ty*8+4];
            *(float4*)&bv[0] = *(const float4*)&Bs[kk][tx*8];
            *(float4*)&bv[4] = *(const float4*)&Bs[kk][tx*8+4];
#pragma unroll
            for (int i = 0; i < 8; i++)
#pragma unroll
                for (int j = 0; j < 8; j++) acc[i][j] += av[i]*bv[j];
        }
        __syncthreads();
    }

#pragma unroll
    for (int i = 0; i < 8; i++) {
        int row = m0 + ty*8 + i;
        float* Crow = Cb + (long)row*ldc + n0 + tx*8;
        if (n0 + tx*8 + 4 <= N) {
            *(float4*)Crow = make_float4(acc[i][0],acc[i][1],acc[i][2],acc[i][3]);
        }
        if (n0 + tx*8 + 8 <= N) {
            *(float4*)(Crow+4) = make_float4(acc[i][4],acc[i][5],acc[i][6],acc[i][7]);
        }
    }
}

// ---------------- causal depthwise conv (width 4) + SiLU ----------------
__global__ void conv_silu_kernel(const float* __restrict__ conv_w,
                                 const float* __restrict__ conv_b)
{
    int cc = blockIdx.x * 256 + threadIdx.x;
    int r = blockIdx.y;
    int l = r & (L_ - 1);
    float acc = conv_b[cc];
    const float* col = g_zx + (size_t)r * DPJA + DI + cc;
#pragma unroll
    for (int w = 0; w < 4; w++) {
        int lp = l - 3 + w;
        if (lp >= 0) acc += col[(long)(w - 3) * DPJA] * conv_w[cc*4 + w];
    }
    float s = acc / (1.0f + __expf(-acc));
    g_xBC[(size_t)r * CD + cc] = s;
}

// ---------------- dt softplus + within-chunk cumsum of dt*A (parallel scan) ----------------
__global__ __launch_bounds__(256) void dt_cumsum_kernel(const float* __restrict__ dt_bias,
                                                        const float* __restrict__ A_log)
{
    __shared__ float wsum[8];
    const int chunk = blockIdx.x;
    const int h = blockIdx.y;
    const int i = threadIdx.x;
    const int lane = i & 31, wid = i >> 5;
    const int r = chunk * CK + i;

    float Ahd = -expf(A_log[h]);
    float x = g_zx[(size_t)r * DPJA + DI + CD + h] + dt_bias[h];
    float dt = fmaxf(x, 0.f) + log1pf(expf(-fabsf(x)));
    g_dt[r*NH + h] = dt;

    float v = dt * Ahd;
#pragma unroll
    for (int o = 1; o < 32; o <<= 1) {
        float n = __shfl_up_sync(0xffffffffu, v, o);
        if (lane >= o) v += n;
    }
    if (lane == 31) wsum[wid] = v;
    __syncthreads();
    float add = 0.f;
#pragma unroll
    for (int wq = 0; wq < 8; wq++) {
        float ws = wsum[wq];
        add += (wq < wid) ? ws : 0.f;
    }
    g_dacs[r*NH + h] = v + add;
}

// ---------------- states via fp16 MMA: S[p][n] = sum_s (w_s x[s][p]) B[s][n] ----------------
// smem: ws float[256] @0 ; At half[64][264] @1024 ; Bt half[128][264] @1024+33792
#define ST_SMEM (1024 + 64*264*2 + 128*264*2)   // 102400 bytes

__global__ __launch_bounds__(256, 2) void states_tc()
{
    extern __shared__ char sm0[];
    float* ws = (float*)sm0;
    __half* At = (__half*)(sm0 + 1024);
    __half* Bt = (__half*)(sm0 + 1024 + 64*264*2);

    const int chunk = blockIdx.x, h = blockIdx.y, base = chunk * CK;
    const int tid = threadIdx.x;

    {
        float dl = g_dacs[(base + CK - 1)*NH + h];
        float dv = g_dacs[(base + tid)*NH + h];
        ws[tid] = __expf(dl - dv) * g_dt[(base + tid)*NH + h];
    }
    __syncthreads();

    // At[p][s] = ws[s] * x[s][p]
#pragma unroll 4
    for (int e = 0; e < 64; e++) {
        int idx = tid + e * 256;
        int p = idx & 63, s = idx >> 6;
        float x = g_xBC[(size_t)(base + s) * CD + h * 64 + p];
        At[p * 264 + s] = __float2half_rn(ws[s] * x);
    }
    // Bt[n][s] = B[s][n]
#pragma unroll 4
    for (int e = 0; e < 128; e++) {
        int idx = tid + e * 256;
        int n = idx & 127, s = idx >> 7;
        Bt[n * 264 + s] = __float2half_rn(g_xBC[(size_t)(base + s) * CD + DI + n]);
    }
    __syncthreads();

    const int wid = tid >> 5, lane = tid & 31;
    const int wm = (wid & 1) * 32;     // p: 2 warps x 32
    const int wn = (wid >> 1) * 32;    // n: 4 warps x 32
    const int fr = lane & 15, fch = (lane >> 4) * 8;

    float acc[2][4][4];
#pragma unroll
    for (int a = 0; a < 2; a++)
#pragma unroll
        for (int b = 0; b < 4; b++)
#pragma unroll
            for (int c = 0; c < 4; c++) acc[a][b][c] = 0.f;

#pragma unroll
    for (int ks = 0; ks < 16; ks++) {
        uint32_t af[2][4];
#pragma unroll
        for (int mb = 0; mb < 2; mb++)
            LDSM4(af[mb], smem_u32(At + (wm + mb * 16 + fr) * 264 + ks * 16 + fch));
        uint32_t bf[2][4];
#pragma unroll
        for (int nb2 = 0; nb2 < 2; nb2++)
            LDSM4(bf[nb2], smem_u32(Bt + (wn + nb2 * 16 + fr) * 264 + ks * 16 + fch));
#pragma unroll
        for (int mb = 0; mb < 2; mb++)
#pragma unroll
            for (int nb = 0; nb < 4; nb++)
                MMAF16(acc[mb][nb], af[mb], bf[nb >> 1][nb & 1], bf[nb >> 1][(nb & 1) + 2]);
    }

    size_t obase = (size_t)(chunk * NH + h) * DH * NS;
    const int er = lane >> 2, ec = (lane & 3) * 2;
#pragma unroll
    for (int mb = 0; mb < 2; mb++) {
        int p0 = wm + mb * 16 + er;
#pragma unroll
        for (int nb = 0; nb < 4; nb++) {
            int col = wn + nb * 8 + ec;
            *(float2*)&g_states[obase + (size_t)p0 * NS + col] =
                make_float2(acc[mb][nb][0], acc[mb][nb][1]);
            *(float2*)&g_states[obase + (size_t)(p0 + 8) * NS + col] =
                make_float2(acc[mb][nb][2], acc[mb][nb][3]);
        }
    }
}

// ---------------- inter-chunk scan ----------------
__global__ void scan_kernel()
{
    int idx = blockIdx.x * 256 + threadIdx.x;
    int h = (idx >> 13) & 63;
    int b = idx >> 19;
    float s = 0.f;
    for (int c = 0; c < 16; c++) {
        size_t off = ((size_t)(b*16 + c)*NH + h)*DH*NS + (idx & 8191);
        g_prev[off] = s;
        float dec = __expf(g_dacs[(size_t)(b*L_ + c*CK + CK - 1)*NH + h]);
        s = s * dec + g_states[off];
    }
}

// ---------------- y via fp16 MMA: y = M@x + (ei*C)@prev^T + Dp*x ----------------
// smem bytes: das[256]f @0 | q[256]f @1024 | rqd[256]f @2048 | ei[256]f @3072 |
//             Sarr[8]+PP[64]f @4096 (512B) | xT half[64][264] @4608 |
//             prevB half[64][136] @38400 | Mt half[256][40] @55808 ; total 76288
#define YTC_SMEM 76288

__global__ __launch_bounds__(256, 2) void y_tc(const float* __restrict__ Dp)
{
    extern __shared__ char sm1[];
    float* das  = (float*)sm1;
    float* q    = das + 256;
    float* rqd  = q + 256;
    float* ei   = rqd + 256;
    float* Sarr = ei + 256;          // 8
    float* PP   = Sarr + 8;          // 64
    __half* xT    = (__half*)(sm1 + 4608);
    __half* prevB = (__half*)(sm1 + 38400);
    __half* Mt    = (__half*)(sm1 + 55808);

    const int chunk = blockIdx.x, h = blockIdx.y, base = chunk * CK;
    const int tid = threadIdx.x;
    const int wid = tid >> 5, lane = tid & 31;

    das[tid] = g_dacs[(base + tid)*NH + h];

    // xT[p][s] = x[s][p] fp16
#pragma unroll 4
    for (int e = 0; e < 64; e++) {
        int idx = tid + e * 256;
        int p = idx & 63, s = idx >> 6;
        xT[p * 264 + s] = __float2half_rn(g_xBC[(size_t)(base + s) * CD + h * 64 + p]);
    }
    // prevB[p][n]
    {
        size_t pb = (size_t)(chunk * NH + h) * DH * NS;
#pragma unroll 4
        for (int e = 0; e < 32; e++) {
            int idx = tid + e * 256;
            int p = idx >> 7, n = idx & 127;
            prevB[p * 136 + n] = __float2half_rn(g_prev[pb + idx]);
        }
    }
    __syncthreads();
    {
        int si = tid >> 5;
        float ref = das[si * 32];
        float d = das[tid];
        q[tid]   = __expf(d - ref);                               // <= 1
        rqd[tid] = __expf(ref - d) * g_dt[(base + tid)*NH + h];   // <= e^51 * dt
        ei[tid]  = __expf(d);
        if (tid < 8)
            Sarr[tid] = (tid == 0) ? 1.f : __expf(das[tid*32] - das[tid*32 - 32]);
    }
    __syncthreads();
    if (tid < 64) {
        int si = tid >> 3, sj = tid & 7;
        float p = 0.f;
        if (si >= sj) {
            p = 1.f;
            for (int t = sj + 1; t <= si; t++) p *= Sarr[t];
        }
        PP[tid] = p;
    }
    __syncthreads();

    // warp grid: 4 warps along i (64 each), 2 along p (32 each)
    const int wm = (wid >> 1) * 64;
    const int wn = (wid & 1) * 32;
    const int fr = lane & 15, fch = (lane >> 4) * 8;

    float acc[4][4][4];
#pragma unroll
    for (int a = 0; a < 4; a++)
#pragma unroll
        for (int b = 0; b < 4; b++)
#pragma unroll
            for (int c = 0; c < 4; c++) acc[a][b][c] = 0.f;

    // ---- y_diag: 8 j-tiles of 32 (one segment each) ----
    const float* cbb = g_CBt + (size_t)chunk * CK * CK;
    for (int jt = 0; jt < 8; jt++) {
        const int j0 = jt * 32;
        {
            const int i = tid;
            const float fq = q[i] * PP[(i >> 5) * 8 + jt];
            const float* cbp = cbb + (size_t)j0 * CK + i;
            __half2* mrow = (__half2*)(Mt + i * 40);
#pragma unroll
            for (int jp = 0; jp < 16; jp++) {
                int j  = 2 * jp;
                int jj = j0 + j;
                float v0 = (jj     <= i) ? cbp[(size_t)j * CK]     * fq * rqd[jj]     : 0.f;
                float v1 = (jj + 1 <= i) ? cbp[(size_t)(j+1) * CK] * fq * rqd[jj + 1] : 0.f;
                mrow[jp] = __halves2half2(__float2half_rn(v0), __float2half_rn(v1));
            }
        }
        __syncthreads();
        if (j0 < wm + 64) {
#pragma unroll
            for (int kk = 0; kk < 2; kk++) {
                uint32_t af[4][4];
#pragma unroll
                for (int mb = 0; mb < 4; mb++)
                    LDSM4(af[mb], smem_u32(Mt + (wm + mb * 16 + fr) * 40 + kk * 16 + fch));
                uint32_t bf[2][4];
#pragma unroll
                for (int nb2 = 0; nb2 < 2; nb2++)
                    LDSM4(bf[nb2], smem_u32(xT + (wn + nb2 * 16 + fr) * 264 + j0 + kk * 16 + fch));
#pragma unroll
                for (int mb = 0; mb < 4; mb++)
#pragma unroll
                    for (int nb = 0; nb < 4; nb++)
                        MMAF16(acc[mb][nb], af[mb], bf[nb >> 1][nb & 1], bf[nb >> 1][(nb & 1) + 2]);
            }
        }
        __syncthreads();
    }

    // ---- y_off: 4 n-tiles of 32 (Ct reuses Mt buffer) ----
    for (int nt = 0; nt < 4; nt++) {
        const int n0 = nt * 32;
        {
            const int i = tid;
            const float e = ei[i];
            const float* cp = &g_xBC[(size_t)(base + i) * CD + DI + NS + n0];
            __half2* mrow = (__half2*)(Mt + i * 40);
#pragma unroll
            for (int j4 = 0; j4 < 8; j4++) {
                float4 v = *(const float4*)(cp + j4 * 4);
                mrow[j4 * 2 + 0] = __halves2half2(__float2half_rn(e * v.x), __float2half_rn(e * v.y));
                mrow[j4 * 2 + 1] = __halves2half2(__float2half_rn(e * v.z), __float2half_rn(e * v.w));
            }
        }
        __syncthreads();
#pragma unroll
        for (int kk = 0; kk < 2; kk++) {
            uint32_t af[4][4];
#pragma unroll
            for (int mb = 0; mb < 4; mb++)
                LDSM4(af[mb], smem_u32(Mt + (wm + mb * 16 + fr) * 40 + kk * 16 + fch));
            uint32_t bf[2][4];
#pragma unroll
            for (int nb2 = 0; nb2 < 2; nb2++)
                LDSM4(bf[nb2], smem_u32(prevB + (wn + nb2 * 16 + fr) * 136 + n0 + kk * 16 + fch));
#pragma unroll
            for (int mb = 0; mb < 4; mb++)
#pragma unroll
                for (int nb = 0; nb < 4; nb++)
                    MMAF16(acc[mb][nb], af[mb], bf[nb >> 1][nb & 1], bf[nb >> 1][(nb & 1) + 2]);
        }
        __syncthreads();
    }

    // ---- epilogue: y = acc + Dp[h] * x ----
    const float dph = Dp[h];
    const int er = lane >> 2, ec = (lane & 3) * 2;
#pragma unroll
    for (int mb = 0; mb < 4; mb++) {
        int i0 = wm + mb * 16 + er;
#pragma unroll
        for (int nb = 0; nb < 4; nb++) {
            int p = wn + nb * 8 + ec;
            float x00 = __half2float(xT[(size_t)p * 264 + i0]);
            float x01 = __half2float(xT[(size_t)(p + 1) * 264 + i0]);
            float x10 = __half2float(xT[(size_t)p * 264 + i0 + 8]);
            float x11 = __half2float(xT[(size_t)(p + 1) * 264 + i0 + 8]);
            *(float2*)&g_y[(size_t)(base + i0) * DI + h * 64 + p] =
                make_float2(acc[mb][nb][0] + dph * x00, acc[mb][nb][1] + dph * x01);
            *(float2*)&g_y[(size_t)(base + i0 + 8) * DI + h * 64 + p] =
                make_float2(acc[mb][nb][2] + dph * x10, acc[mb][nb][3] + dph * x11);
        }
    }
}

// ---------------- gate (silu(z)) + RMSNorm; writes fp16 operand directly ----------------
__global__ __launch_bounds__(256) void gate_norm_kernel(const float* __restrict__ norm_w)
{
    __shared__ float buf[DI];
    __shared__ float red[8];
    int r = blockIdx.x;
    int tid = threadIdx.x;
    float ss = 0.f;
#pragma unroll
    for (int e = 0; e < 16; e++) {
        int c = tid + e*256;
        float y = g_y[(size_t)r*DI + c];
        float z = g_zx[(size_t)r*DPJA + c];
        float g = y * (z / (1.f + __expf(-z)));
        buf[c] = g;
        ss += g*g;
    }
#pragma unroll
    for (int o = 16; o > 0; o >>= 1) ss += __shfl_xor_sync(0xffffffffu, ss, o);
    if ((tid & 31) == 0) red[tid >> 5] = ss;
    __syncthreads();
    float tot = 0.f;
#pragma unroll
    for (int q = 0; q < 8; q++) tot += red[q];
    float scale = rsqrtf(tot / (float)DI + 1e-5f);
#pragma unroll
    for (int e = 0; e < 16; e++) {
        int c = tid + e*256;
        g_yh[(size_t)r*DI + c] = __float2half_rn(buf[c] * scale * norm_w[c]);
    }
}

// ---------------- launch ----------------
extern "C" void kernel_launch(void* const* d_in, const int* in_sizes, int n_in,
                              void* d_out, int out_size)
{
    const float* u       = (const float*)d_in[0];
    const float* W_in    = (const float*)d_in[1];
    const float* conv_w  = (const float*)d_in[2];
    const float* conv_b  = (const float*)d_in[3];
    const float* dt_bias = (const float*)d_in[4];
    const float* A_log   = (const float*)d_in[5];
    const float* Dp      = (const float*)d_in[6];
    const float* norm_w  = (const float*)d_in[7];
    const float* W_out   = (const float*)d_in[8];
    float* out = (float*)d_out;

    float *zx, *xbc, *cbt;
    __half *uh, *wi1, *yh, *wo1;
    cudaGetSymbolAddress((void**)&zx,  g_zx);
    cudaGetSymbolAddress((void**)&xbc, g_xBC);
    cudaGetSymbolAddress((void**)&cbt, g_CBt);
    cudaGetSymbolAddress((void**)&uh,  g_uh);
    cudaGetSymbolAddress((void**)&wi1, g_wi1);
    cudaGetSymbolAddress((void**)&yh,  g_yh);
    cudaGetSymbolAddress((void**)&wo1, g_wo1);

    cudaFuncSetAttribute(gemm_f16, cudaFuncAttributeMaxDynamicSharedMemorySize, FGEMM_SMEM);
    cudaFuncSetAttribute(states_tc, cudaFuncAttributeMaxDynamicSharedMemorySize, ST_SMEM);
    cudaFuncSetAttribute(y_tc, cudaFuncAttributeMaxDynamicSharedMemorySize, YTC_SMEM);

    // convert inputs for GEMM1
    {
        long n4 = (long)RW * DM / 4;
        cvt_h1_kernel<<<(int)((n4 + 255) / 256), 256>>>(u, uh, n4);
    }
    {
        long n4 = (long)DPJA * DM / 4;
        cvt_h1_pad_kernel<<<(int)((n4 + 255) / 256), 256>>>(W_in, wi1, n4, DPJ, DM/4);
    }

    // 1) in-proj (fp16 1-pass tensor GEMM)
    gemm_f16<<<dim3(DPJA/128, RW/128), 256, FGEMM_SMEM>>>(uh, wi1, zx, DM, DPJA);

    // 2) conv + silu
    conv_silu_kernel<<<dim3(CD/256, RW), 256>>>(conv_w, conv_b);

    // 3) dt softplus + per-chunk cumsum
    dt_cumsum_kernel<<<dim3(NCH, NH), 256>>>(dt_bias, A_log);

    // 4) per-chunk CBt (fp32)
    dim3 g2(2, 2, NCH);
    sgemm_nt<<<g2, 256>>>(xbc + DI, xbc + DI + NS, cbt,
                          CK, CK, NS, CD, CD, CK,
                          (long)CK*CD, (long)CK*CD, (long)CK*CK);

    // 5) states (fp16 MMA)
    states_tc<<<dim3(NCH, NH), 256, ST_SMEM>>>();

    // 6) inter-chunk scan
    scan_kernel<<<4096, 256>>>();

    // 7) fused y (fp16 MMA, segment-factorized decay)
    y_tc<<<dim3(NCH, NH), 256, YTC_SMEM>>>(Dp);

    // 8) gate + RMSNorm (writes yh fp16 directly)
    gate_norm_kernel<<<RW, 256>>>(norm_w);

    // convert W_out for GEMM2
    {
        long n4 = (long)DM * DI / 4;
        cvt_h1_kernel<<<(int)((n4 + 255) / 256), 256>>>(W_out, wo1, n4);
    }

    // 9) out-proj (fp16 1-pass tensor GEMM)
    gemm_f16<<<dim3(DM/128, RW/128), 256, FGEMM_SMEM>>>(yh, wo1, out, DI, DM);
}

// round 11
// speedup vs baseline: 4.8869x; 1.0339x over previous
#include <cuda_runtime.h>
#include <cuda_fp16.h>
#include <math.h>
#include <stdint.h>

// ---------------- problem constants ----------------
#define L_   4096
#define DM   2048          // D_MODEL
#define DI   4096          // D_INNER
#define NH   64            // N_HEADS
#define DH   64            // D_HEAD
#define NS   128           // D_STATE
#define CD   4352          // CONV_DIM
#define DPJ  8512          // D_IN_PROJ
#define DPJA 8704          // padded to 68*128 for GEMM tiles
#define CK   256           // CHUNK
#define NCH  32            // total chunks
#define RW   8192          // total rows = B*L

// ---------------- scratch (device globals; no allocations) ----------------
__device__ float g_zx[(size_t)RW * DPJA];
__device__ float g_xBC[(size_t)RW * CD];
__device__ float g_dt[RW * NH];
__device__ float g_dacs[RW * NH];
__device__ float g_CBt[NCH * CK * CK];
__device__ float g_states[(size_t)NCH * NH * DH * NS];
__device__ float g_prev[(size_t)NCH * NH * DH * NS];
__device__ __half g_y[(size_t)RW * DI];        // y pre-norm (fp16)
// fp16 operands (single precision-level, 1-pass GEMMs)
__device__ __half g_uh[(size_t)RW * DM];
__device__ __half g_wi1[(size_t)DPJA * DM];
__device__ __half g_yh[(size_t)RW * DI];
__device__ __half g_wo1[(size_t)DM * DI];

// ================= PTX helpers (portable, compute_103-safe) =================
__device__ __forceinline__ uint32_t smem_u32(const void* p) {
    uint32_t a;
    asm("{ .reg .u64 t; cvta.to.shared.u64 t, %1; cvt.u32.u64 %0, t; }" : "=r"(a) : "l"(p));
    return a;
}
#define CPA16(dst, src) \
    asm volatile("cp.async.cg.shared.global [%0], [%1], 16;" :: "r"(dst), "l"(src) : "memory")

#define LDSM4(r, adr)                                                            \
    asm volatile("ldmatrix.sync.aligned.m8n8.x4.shared.b16 {%0,%1,%2,%3}, [%4];" \
        : "=r"((r)[0]), "=r"((r)[1]), "=r"((r)[2]), "=r"((r)[3]) : "r"(adr))

#define MMAF16(c, a, b0, b1)                                                     \
    asm volatile("mma.sync.aligned.m16n8k16.row.col.f32.f16.f16.f32 "            \
        "{%0,%1,%2,%3}, {%4,%5,%6,%7}, {%8,%9}, {%0,%1,%2,%3};"                  \
        : "+f"((c)[0]), "+f"((c)[1]), "+f"((c)[2]), "+f"((c)[3])                  \
        : "r"((a)[0]), "r"((a)[1]), "r"((a)[2]), "r"((a)[3]), "r"(b0), "r"(b1))

// ================= conversion kernels =================
__global__ __launch_bounds__(256) void cvt_h1_kernel(
    const float* __restrict__ src, __half* __restrict__ dst, long n4)
{
    long i = (long)blockIdx.x * 256 + threadIdx.x;
    if (i >= n4) return;
    float4 v = ((const float4*)src)[i];
    ((__half2*)dst)[2*i]   = __halves2half2(__float2half_rn(v.x), __float2half_rn(v.y));
    ((__half2*)dst)[2*i+1] = __halves2half2(__float2half_rn(v.z), __float2half_rn(v.w));
}

__global__ __launch_bounds__(256) void cvt_h1_pad_kernel(
    const float* __restrict__ src, __half* __restrict__ dst,
    long n4, long rows_src, long cols4)
{
    long i = (long)blockIdx.x * 256 + threadIdx.x;
    if (i >= n4) return;
    float4 v = make_float4(0.f, 0.f, 0.f, 0.f);
    if (i / cols4 < rows_src) v = ((const float4*)src)[i];
    ((__half2*)dst)[2*i]   = __halves2half2(__float2half_rn(v.x), __float2half_rn(v.y));
    ((__half2*)dst)[2*i+1] = __halves2half2(__float2half_rn(v.z), __float2half_rn(v.w));
}

// ================= fp16 1-pass NT GEMM (now 2 CTAs/SM) =================
#define FSTAGES 3
#define FROWH 40
#define FTILE (128 * FROWH)
#define FSTAGE (2 * FTILE)
#define FGEMM_SMEM (FSTAGES * FSTAGE * 2)      // 61440 B -> 2 CTAs co-resident

__global__ __launch_bounds__(256, 2) void gemm_f16(
    const __half* __restrict__ A1, const __half* __restrict__ B1,
    float* __restrict__ C, int Ktot, int ldc)
{
    extern __shared__ __half fsm[];
    const int tid = threadIdx.x;
    const int wid = tid >> 5;
    const int lane = tid & 31;

    const int m0 = blockIdx.y * 128;
    const int n0 = blockIdx.x * 128;

    const int lrow = tid >> 2;
    const int lch  = (tid & 3) * 8;

    const __half* a1p = A1 + (size_t)m0 * Ktot;
    const __half* b1p = B1 + (size_t)n0 * Ktot;

    auto load_stage = [&](int s, int k0) {
        __half* st = fsm + s * FSTAGE;
#pragma unroll
        for (int q = 0; q < 2; q++) {
            int row = lrow + q * 64;
            uint32_t d = smem_u32(st + row * FROWH + lch);
            CPA16(d,             a1p + (size_t)row * Ktot + k0 + lch);
            CPA16(d + FTILE * 2, b1p + (size_t)row * Ktot + k0 + lch);
        }
        asm volatile("cp.async.commit_group;" ::: "memory");
    };

    const int wm = (wid & 1) * 64;
    const int wn = (wid >> 1) * 32;
    const int fr = lane & 15;
    const int fch = (lane >> 4) * 8;

    float acc[4][4][4];
#pragma unroll
    for (int a = 0; a < 4; a++)
#pragma unroll
        for (int b = 0; b < 4; b++)
#pragma unroll
            for (int c = 0; c < 4; c++) acc[a][b][c] = 0.f;

    const int KT = Ktot / 32;
    load_stage(0, 0);
    load_stage(1, 32);

    int cur = 0, nxt = 2;
    for (int kt = 0; kt < KT; kt++) {
        if (kt < KT - 1) {
            asm volatile("cp.async.wait_group 1;" ::: "memory");
        } else {
            asm volatile("cp.async.wait_group 0;" ::: "memory");
        }
        __syncthreads();
        if (kt + 2 < KT) load_stage(nxt, (kt + 2) * 32);

        const __half* st = fsm + cur * FSTAGE;
#pragma unroll
        for (int kk = 0; kk < 2; kk++) {
            const int kof = kk * 16;
            uint32_t af[4][4];
#pragma unroll
            for (int mb = 0; mb < 4; mb++) {
                uint32_t adr = smem_u32(st + (wm + mb * 16 + fr) * FROWH + kof + fch);
                LDSM4(af[mb], adr);
            }
            uint32_t bf[2][4];
#pragma unroll
            for (int nb2 = 0; nb2 < 2; nb2++) {
                uint32_t adr = smem_u32(st + FTILE + (wn + nb2 * 16 + fr) * FROWH + kof + fch);
                LDSM4(bf[nb2], adr);
            }
#pragma unroll
            for (int mb = 0; mb < 4; mb++)
#pragma unroll
                for (int nb = 0; nb < 4; nb++)
                    MMAF16(acc[mb][nb], af[mb], bf[nb >> 1][nb & 1], bf[nb >> 1][(nb & 1) + 2]);
        }
        cur = (cur == 2) ? 0 : cur + 1;
        nxt = (nxt == 2) ? 0 : nxt + 1;
    }

    const int er = lane >> 2;
    const int ec = (lane & 3) * 2;
#pragma unroll
    for (int mb = 0; mb < 4; mb++) {
#pragma unroll
        for (int nb = 0; nb < 4; nb++) {
            float* p0 = C + (size_t)(m0 + wm + mb * 16 + er) * ldc + n0 + wn + nb * 8 + ec;
            float* p1 = p0 + 8 * ldc;
            *(float2*)p0 = make_float2(acc[mb][nb][0], acc[mb][nb][1]);
            *(float2*)p1 = make_float2(acc[mb][nb][2], acc[mb][nb][3]);
        }
    }
}

// ---------------- fp32 NT SGEMM (per-chunk C@B^T) ----------------
__global__ __launch_bounds__(256) void sgemm_nt(
    const float* __restrict__ A, const float* __restrict__ Bm, float* __restrict__ C,
    int M, int N, int K, int lda, int ldb, int ldc,
    long sA, long sB, long sC)
{
    const float* Ab = A + (long)blockIdx.z * sA;
    const float* Bb = Bm + (long)blockIdx.z * sB;
    float* Cb = C + (long)blockIdx.z * sC;

    __shared__ float As[16][128];
    __shared__ float Bs[16][128];

    const int tid = threadIdx.x;
    const int m0 = blockIdx.y * 128;
    const int n0 = blockIdx.x * 128;
    const int tx = tid & 15;
    const int ty = tid >> 4;

    const int lrow = tid >> 1;
    const int lk = (tid & 1) * 8;
    const float* Aload = Ab + (long)(m0 + lrow) * lda + lk;
    const float* Bload = Bb + (long)(n0 + lrow) * ldb + lk;
    const bool bvalid = (n0 + lrow) < N;

    float acc[8][8];
#pragma unroll
    for (int i = 0; i < 8; i++)
#pragma unroll
        for (int j = 0; j < 8; j++) acc[i][j] = 0.0f;

    float4 a0 = *(const float4*)(Aload);
    float4 a1 = *(const float4*)(Aload + 4);
    float4 b0 = make_float4(0.f,0.f,0.f,0.f), b1 = make_float4(0.f,0.f,0.f,0.f);
    if (bvalid) { b0 = *(const float4*)(Bload); b1 = *(const float4*)(Bload + 4); }

    for (int k0 = 0; k0 < K; k0 += 16) {
        As[lk+0][lrow] = a0.x; As[lk+1][lrow] = a0.y; As[lk+2][lrow] = a0.z; As[lk+3][lrow] = a0.w;
        As[lk+4][lrow] = a1.x; As[lk+5][lrow] = a1.y; As[lk+6][lrow] = a1.z; As[lk+7][lrow] = a1.w;
        Bs[lk+0][lrow] = b0.x; Bs[lk+1][lrow] = b0.y; Bs[lk+2][lrow] = b0.z; Bs[lk+3][lrow] = b0.w;
        Bs[lk+4][lrow] = b1.x; Bs[lk+5][lrow] = b1.y; Bs[lk+6][lrow] = b1.z; Bs[lk+7][lrow] = b1.w;
        __syncthreads();
        if (k0 + 16 < K) {
            a0 = *(const float4*)(Aload + k0 + 16);
            a1 = *(const float4*)(Aload + k0 + 20);
            if (bvalid) {
                b0 = *(const float4*)(Bload + k0 + 16);
                b1 = *(const float4*)(Bload + k0 + 20);
            }
        }
#pragma unroll
        for (int kk = 0; kk < 16; kk++) {
            float av[8], bv[8];
            *(float4*)&av[0] = *(const float4*)&As[kk][ty*8];
            *(float4*)&av[4] = *(const float4*)&As[kk][ty*8+4];
            *(float4*)&bv[0] = *(const float4*)&Bs[kk][tx*8];
            *(float4*)&bv[4] = *(const float4*)&Bs[kk][tx*8+4];
#pragma unroll
            for (int i = 0; i < 8; i++)
#pragma unroll
                for (int j = 0; j < 8; j++) acc[i][j] += av[i]*bv[j];
        }
        __syncthreads();
    }

#pragma unroll
    for (int i = 0; i < 8; i++) {
        int row = m0 + ty*8 + i;
        float* Crow = Cb + (long)row*ldc + n0 + tx*8;
        if (n0 + tx*8 + 4 <= N) {
            *(float4*)Crow = make_float4(acc[i][0],acc[i][1],acc[i][2],acc[i][3]);
        }
        if (n0 + tx*8 + 8 <= N) {
            *(float4*)(Crow+4) = make_float4(acc[i][4],acc[i][5],acc[i][6],acc[i][7]);
        }
    }
}

// ---------------- tiled causal depthwise conv (width 4) + SiLU ----------------
// block: 16 rows x 256 cols; smem tile 19x256 (reuse across the 4 taps)
#define CT_ROWS 16
__global__ __launch_bounds__(256) void conv_silu_kernel(const float* __restrict__ conv_w,
                                                        const float* __restrict__ conv_b)
{
    __shared__ float ts[CT_ROWS + 3][256];
    const int c0 = blockIdx.x * 256;
    const int r0 = blockIdx.y * CT_ROWS;
    const int tid = threadIdx.x;
    const int cc = c0 + tid;
    const int batch_start = r0 & ~(L_ - 1);

    const float* src = g_zx + DI + cc;
#pragma unroll
    for (int rr = 0; rr < CT_ROWS + 3; rr++) {
        int x = r0 - 3 + rr;
        ts[rr][tid] = (x >= batch_start) ? src[(size_t)x * DPJA] : 0.f;
    }
    __syncthreads();

    const float cw0 = conv_w[cc*4+0], cw1 = conv_w[cc*4+1];
    const float cw2 = conv_w[cc*4+2], cw3 = conv_w[cc*4+3];
    const float cb = conv_b[cc];
#pragma unroll
    for (int rr = 0; rr < CT_ROWS; rr++) {
        float acc = cb + ts[rr][tid]*cw0 + ts[rr+1][tid]*cw1
                       + ts[rr+2][tid]*cw2 + ts[rr+3][tid]*cw3;
        float s = acc / (1.0f + __expf(-acc));
        g_xBC[(size_t)(r0 + rr) * CD + cc] = s;
    }
}

// ---------------- dt softplus + within-chunk cumsum of dt*A (parallel scan) ----------------
__global__ __launch_bounds__(256) void dt_cumsum_kernel(const float* __restrict__ dt_bias,
                                                        const float* __restrict__ A_log)
{
    __shared__ float wsum[8];
    const int chunk = blockIdx.x;
    const int h = blockIdx.y;
    const int i = threadIdx.x;
    const int lane = i & 31, wid = i >> 5;
    const int r = chunk * CK + i;

    float Ahd = -expf(A_log[h]);
    float x = g_zx[(size_t)r * DPJA + DI + CD + h] + dt_bias[h];
    float dt = fmaxf(x, 0.f) + log1pf(expf(-fabsf(x)));
    g_dt[r*NH + h] = dt;

    float v = dt * Ahd;
#pragma unroll
    for (int o = 1; o < 32; o <<= 1) {
        float n = __shfl_up_sync(0xffffffffu, v, o);
        if (lane >= o) v += n;
    }
    if (lane == 31) wsum[wid] = v;
    __syncthreads();
    float add = 0.f;
#pragma unroll
    for (int wq = 0; wq < 8; wq++) {
        float ws = wsum[wq];
        add += (wq < wid) ? ws : 0.f;
    }
    g_dacs[r*NH + h] = v + add;
}

// ---------------- states via fp16 MMA ----------------
#define ST_SMEM (1024 + 64*264*2 + 128*264*2)

__global__ __launch_bounds__(256, 2) void states_tc()
{
    extern __shared__ char sm0[];
    float* ws = (float*)sm0;
    __half* At = (__half*)(sm0 + 1024);
    __half* Bt = (__half*)(sm0 + 1024 + 64*264*2);

    const int chunk = blockIdx.x, h = blockIdx.y, base = chunk * CK;
    const int tid = threadIdx.x;

    {
        float dl = g_dacs[(base + CK - 1)*NH + h];
        float dv = g_dacs[(base + tid)*NH + h];
        ws[tid] = __expf(dl - dv) * g_dt[(base + tid)*NH + h];
    }
    __syncthreads();

#pragma unroll 4
    for (int e = 0; e < 64; e++) {
        int idx = tid + e * 256;
        int p = idx & 63, s = idx >> 6;
        float x = g_xBC[(size_t)(base + s) * CD + h * 64 + p];
        At[p * 264 + s] = __float2half_rn(ws[s] * x);
    }
#pragma unroll 4
    for (int e = 0; e < 128; e++) {
        int idx = tid + e * 256;
        int n = idx & 127, s = idx >> 7;
        Bt[n * 264 + s] = __float2half_rn(g_xBC[(size_t)(base + s) * CD + DI + n]);
    }
    __syncthreads();

    const int wid = tid >> 5, lane = tid & 31;
    const int wm = (wid & 1) * 32;
    const int wn = (wid >> 1) * 32;
    const int fr = lane & 15, fch = (lane >> 4) * 8;

    float acc[2][4][4];
#pragma unroll
    for (int a = 0; a < 2; a++)
#pragma unroll
        for (int b = 0; b < 4; b++)
#pragma unroll
            for (int c = 0; c < 4; c++) acc[a][b][c] = 0.f;

#pragma unroll
    for (int ks = 0; ks < 16; ks++) {
        uint32_t af[2][4];
#pragma unroll
        for (int mb = 0; mb < 2; mb++)
            LDSM4(af[mb], smem_u32(At + (wm + mb * 16 + fr) * 264 + ks * 16 + fch));
        uint32_t bf[2][4];
#pragma unroll
        for (int nb2 = 0; nb2 < 2; nb2++)
            LDSM4(bf[nb2], smem_u32(Bt + (wn + nb2 * 16 + fr) * 264 + ks * 16 + fch));
#pragma unroll
        for (int mb = 0; mb < 2; mb++)
#pragma unroll
            for (int nb = 0; nb < 4; nb++)
                MMAF16(acc[mb][nb], af[mb], bf[nb >> 1][nb & 1], bf[nb >> 1][(nb & 1) + 2]);
    }

    size_t obase = (size_t)(chunk * NH + h) * DH * NS;
    const int er = lane >> 2, ec = (lane & 3) * 2;
#pragma unroll
    for (int mb = 0; mb < 2; mb++) {
        int p0 = wm + mb * 16 + er;
#pragma unroll
        for (int nb = 0; nb < 4; nb++) {
            int col = wn + nb * 8 + ec;
            *(float2*)&g_states[obase + (size_t)p0 * NS + col] =
                make_float2(acc[mb][nb][0], acc[mb][nb][1]);
            *(float2*)&g_states[obase + (size_t)(p0 + 8) * NS + col] =
                make_float2(acc[mb][nb][2], acc[mb][nb][3]);
        }
    }
}

// ---------------- inter-chunk scan ----------------
__global__ void scan_kernel()
{
    int idx = blockIdx.x * 256 + threadIdx.x;
    int h = (idx >> 13) & 63;
    int b = idx >> 19;
    float s = 0.f;
    for (int c = 0; c < 16; c++) {
        size_t off = ((size_t)(b*16 + c)*NH + h)*DH*NS + (idx & 8191);
        g_prev[off] = s;
        float dec = __expf(g_dacs[(size_t)(b*L_ + c*CK + CK - 1)*NH + h]);
        s = s * dec + g_states[off];
    }
}

// ---------------- y via fp16 MMA (writes g_y as fp16) ----------------
#define YTC_SMEM 76288

__global__ __launch_bounds__(256, 2) void y_tc(const float* __restrict__ Dp)
{
    extern __shared__ char sm1[];
    float* das  = (float*)sm1;
    float* q    = das + 256;
    float* rqd  = q + 256;
    float* ei   = rqd + 256;
    float* Sarr = ei + 256;
    float* PP   = Sarr + 8;
    __half* xT    = (__half*)(sm1 + 4608);
    __half* prevB = (__half*)(sm1 + 38400);
    __half* Mt    = (__half*)(sm1 + 55808);

    const int chunk = blockIdx.x, h = blockIdx.y, base = chunk * CK;
    const int tid = threadIdx.x;
    const int wid = tid >> 5, lane = tid & 31;

    das[tid] = g_dacs[(base + tid)*NH + h];

#pragma unroll 4
    for (int e = 0; e < 64; e++) {
        int idx = tid + e * 256;
        int p = idx & 63, s = idx >> 6;
        xT[p * 264 + s] = __float2half_rn(g_xBC[(size_t)(base + s) * CD + h * 64 + p]);
    }
    {
        size_t pb = (size_t)(chunk * NH + h) * DH * NS;
#pragma unroll 4
        for (int e = 0; e < 32; e++) {
            int idx = tid + e * 256;
            int p = idx >> 7, n = idx & 127;
            prevB[p * 136 + n] = __float2half_rn(g_prev[pb + idx]);
        }
    }
    __syncthreads();
    {
        int si = tid >> 5;
        float ref = das[si * 32];
        float d = das[tid];
        q[tid]   = __expf(d - ref);
        rqd[tid] = __expf(ref - d) * g_dt[(base + tid)*NH + h];
        ei[tid]  = __expf(d);
        if (tid < 8)
            Sarr[tid] = (tid == 0) ? 1.f : __expf(das[tid*32] - das[tid*32 - 32]);
    }
    __syncthreads();
    if (tid < 64) {
        int si = tid >> 3, sj = tid & 7;
        float p = 0.f;
        if (si >= sj) {
            p = 1.f;
            for (int t = sj + 1; t <= si; t++) p *= Sarr[t];
        }
        PP[tid] = p;
    }
    __syncthreads();

    const int wm = (wid >> 1) * 64;
    const int wn = (wid & 1) * 32;
    const int fr = lane & 15, fch = (lane >> 4) * 8;

    float acc[4][4][4];
#pragma unroll
    for (int a = 0; a < 4; a++)
#pragma unroll
        for (int b = 0; b < 4; b++)
#pragma unroll
            for (int c = 0; c < 4; c++) acc[a][b][c] = 0.f;

    // ---- y_diag ----
    const float* cbb = g_CBt + (size_t)chunk * CK * CK;
    for (int jt = 0; jt < 8; jt++) {
        const int j0 = jt * 32;
        {
            const int i = tid;
            const float fq = q[i] * PP[(i >> 5) * 8 + jt];
            const float* cbp = cbb + (size_t)j0 * CK + i;
            __half2* mrow = (__half2*)(Mt + i * 40);
#pragma unroll
            for (int jp = 0; jp < 16; jp++) {
                int j  = 2 * jp;
                int jj = j0 + j;
                float v0 = (jj     <= i) ? cbp[(size_t)j * CK]     * fq * rqd[jj]     : 0.f;
                float v1 = (jj + 1 <= i) ? cbp[(size_t)(j+1) * CK] * fq * rqd[jj + 1] : 0.f;
                mrow[jp] = __halves2half2(__float2half_rn(v0), __float2half_rn(v1));
            }
        }
        __syncthreads();
        if (j0 < wm + 64) {
#pragma unroll
            for (int kk = 0; kk < 2; kk++) {
                uint32_t af[4][4];
#pragma unroll
                for (int mb = 0; mb < 4; mb++)
                    LDSM4(af[mb], smem_u32(Mt + (wm + mb * 16 + fr) * 40 + kk * 16 + fch));
                uint32_t bf[2][4];
#pragma unroll
                for (int nb2 = 0; nb2 < 2; nb2++)
                    LDSM4(bf[nb2], smem_u32(xT + (wn + nb2 * 16 + fr) * 264 + j0 + kk * 16 + fch));
#pragma unroll
                for (int mb = 0; mb < 4; mb++)
#pragma unroll
                    for (int nb = 0; nb < 4; nb++)
                        MMAF16(acc[mb][nb], af[mb], bf[nb >> 1][nb & 1], bf[nb >> 1][(nb & 1) + 2]);
            }
        }
        __syncthreads();
    }

    // ---- y_off ----
    for (int nt = 0; nt < 4; nt++) {
        const int n0 = nt * 32;
        {
            const int i = tid;
            const float e = ei[i];
            const float* cp = &g_xBC[(size_t)(base + i) * CD + DI + NS + n0];
            __half2* mrow = (__half2*)(Mt + i * 40);
#pragma unroll
            for (int j4 = 0; j4 < 8; j4++) {
                float4 v = *(const float4*)(cp + j4 * 4);
                mrow[j4 * 2 + 0] = __halves2half2(__float2half_rn(e * v.x), __float2half_rn(e * v.y));
                mrow[j4 * 2 + 1] = __halves2half2(__float2half_rn(e * v.z), __float2half_rn(e * v.w));
            }
        }
        __syncthreads();
#pragma unroll
        for (int kk = 0; kk < 2; kk++) {
            uint32_t af[4][4];
#pragma unroll
            for (int mb = 0; mb < 4; mb++)
                LDSM4(af[mb], smem_u32(Mt + (wm + mb * 16 + fr) * 40 + kk * 16 + fch));
            uint32_t bf[2][4];
#pragma unroll
            for (int nb2 = 0; nb2 < 2; nb2++)
                LDSM4(bf[nb2], smem_u32(prevB + (wn + nb2 * 16 + fr) * 136 + n0 + kk * 16 + fch));
#pragma unroll
            for (int mb = 0; mb < 4; mb++)
#pragma unroll
                for (int nb = 0; nb < 4; nb++)
                    MMAF16(acc[mb][nb], af[mb], bf[nb >> 1][nb & 1], bf[nb >> 1][(nb & 1) + 2]);
        }
        __syncthreads();
    }

    // ---- epilogue: y = acc + Dp[h] * x  (fp16 store) ----
    const float dph = Dp[h];
    const int er = lane >> 2, ec = (lane & 3) * 2;
#pragma unroll
    for (int mb = 0; mb < 4; mb++) {
        int i0 = wm + mb * 16 + er;
#pragma unroll
        for (int nb = 0; nb < 4; nb++) {
            int p = wn + nb * 8 + ec;
            float x00 = __half2float(xT[(size_t)p * 264 + i0]);
            float x01 = __half2float(xT[(size_t)(p + 1) * 264 + i0]);
            float x10 = __half2float(xT[(size_t)p * 264 + i0 + 8]);
            float x11 = __half2float(xT[(size_t)(p + 1) * 264 + i0 + 8]);
            *(__half2*)&g_y[(size_t)(base + i0) * DI + h * 64 + p] =
                __halves2half2(__float2half_rn(acc[mb][nb][0] + dph * x00),
                               __float2half_rn(acc[mb][nb][1] + dph * x01));
            *(__half2*)&g_y[(size_t)(base + i0 + 8) * DI + h * 64 + p] =
                __halves2half2(__float2half_rn(acc[mb][nb][2] + dph * x10),
                               __float2half_rn(acc[mb][nb][3] + dph * x11));
        }
    }
}

// ---------------- gate (silu(z)) + RMSNorm; fp16 in, fp16 out ----------------
__global__ __launch_bounds__(256) void gate_norm_kernel(const float* __restrict__ norm_w)
{
    __shared__ float buf[DI];
    __shared__ float red[8];
    int r = blockIdx.x;
    int tid = threadIdx.x;
    float ss = 0.f;
#pragma unroll
    for (int e = 0; e < 16; e++) {
        int c = tid + e*256;
        float y = __half2float(g_y[(size_t)r*DI + c]);
        float z = g_zx[(size_t)r*DPJA + c];
        float g = y * (z / (1.f + __expf(-z)));
        buf[c] = g;
        ss += g*g;
    }
#pragma unroll
    for (int o = 16; o > 0; o >>= 1) ss += __shfl_xor_sync(0xffffffffu, ss, o);
    if ((tid & 31) == 0) red[tid >> 5] = ss;
    __syncthreads();
    float tot = 0.f;
#pragma unroll
    for (int q = 0; q < 8; q++) tot += red[q];
    float scale = rsqrtf(tot / (float)DI + 1e-5f);
#pragma unroll
    for (int e = 0; e < 16; e++) {
        int c = tid + e*256;
        g_yh[(size_t)r*DI + c] = __float2half_rn(buf[c] * scale * norm_w[c]);
    }
}

// ---------------- launch ----------------
extern "C" void kernel_launch(void* const* d_in, const int* in_sizes, int n_in,
                              void* d_out, int out_size)
{
    const float* u       = (const float*)d_in[0];
    const float* W_in    = (const float*)d_in[1];
    const float* conv_w  = (const float*)d_in[2];
    const float* conv_b  = (const float*)d_in[3];
    const float* dt_bias = (const float*)d_in[4];
    const float* A_log   = (const float*)d_in[5];
    const float* Dp      = (const float*)d_in[6];
    const float* norm_w  = (const float*)d_in[7];
    const float* W_out   = (const float*)d_in[8];
    float* out = (float*)d_out;

    float *zx, *xbc, *cbt;
    __half *uh, *wi1, *yh, *wo1;
    cudaGetSymbolAddress((void**)&zx,  g_zx);
    cudaGetSymbolAddress((void**)&xbc, g_xBC);
    cudaGetSymbolAddress((void**)&cbt, g_CBt);
    cudaGetSymbolAddress((void**)&uh,  g_uh);
    cudaGetSymbolAddress((void**)&wi1, g_wi1);
    cudaGetSymbolAddress((void**)&yh,  g_yh);
    cudaGetSymbolAddress((void**)&wo1, g_wo1);

    cudaFuncSetAttribute(gemm_f16, cudaFuncAttributeMaxDynamicSharedMemorySize, FGEMM_SMEM);
    cudaFuncSetAttribute(states_tc, cudaFuncAttributeMaxDynamicSharedMemorySize, ST_SMEM);
    cudaFuncSetAttribute(y_tc, cudaFuncAttributeMaxDynamicSharedMemorySize, YTC_SMEM);

    // convert inputs for GEMM1
    {
        long n4 = (long)RW * DM / 4;
        cvt_h1_kernel<<<(int)((n4 + 255) / 256), 256>>>(u, uh, n4);
    }
    {
        long n4 = (long)DPJA * DM / 4;
        cvt_h1_pad_kernel<<<(int)((n4 + 255) / 256), 256>>>(W_in, wi1, n4, DPJ, DM/4);
    }

    // 1) in-proj (fp16 1-pass tensor GEMM, 2 CTAs/SM)
    gemm_f16<<<dim3(DPJA/128, RW/128), 256, FGEMM_SMEM>>>(uh, wi1, zx, DM, DPJA);

    // 2) conv + silu (tiled)
    conv_silu_kernel<<<dim3(CD/256, RW/CT_ROWS), 256>>>(conv_w, conv_b);

    // 3) dt softplus + per-chunk cumsum
    dt_cumsum_kernel<<<dim3(NCH, NH), 256>>>(dt_bias, A_log);

    // 4) per-chunk CBt (fp32)
    dim3 g2(2, 2, NCH);
    sgemm_nt<<<g2, 256>>>(xbc + DI, xbc + DI + NS, cbt,
                          CK, CK, NS, CD, CD, CK,
                          (long)CK*CD, (long)CK*CD, (long)CK*CK);

    // 5) states (fp16 MMA)
    states_tc<<<dim3(NCH, NH), 256, ST_SMEM>>>();

    // 6) inter-chunk scan
    scan_kernel<<<4096, 256>>>();

    // 7) fused y (fp16 MMA)
    y_tc<<<dim3(NCH, NH), 256, YTC_SMEM>>>(Dp);

    // 8) gate + RMSNorm
    gate_norm_kernel<<<RW, 256>>>(norm_w);

    // convert W_out for GEMM2
    {
        long n4 = (long)DM * DI / 4;
        cvt_h1_kernel<<<(int)((n4 + 255) / 256), 256>>>(W_out, wo1, n4);
    }

    // 9) out-proj (fp16 1-pass tensor GEMM, 2 CTAs/SM)
    gemm_f16<<<dim3(DM/128, RW/128), 256, FGEMM_SMEM>>>(yh, wo1, out, DI, DM);
}

// round 12
// speedup vs baseline: 4.8918x; 1.0010x over previous
#include <cuda_runtime.h>
#include <cuda_fp16.h>
#include <math.h>
#include <stdint.h>

// ---------------- problem constants ----------------
#define L_   4096
#define DM   2048          // D_MODEL
#define DI   4096          // D_INNER
#define NH   64            // N_HEADS
#define DH   64            // D_HEAD
#define NS   128           // D_STATE
#define CD   4352          // CONV_DIM
#define DPJ  8512          // D_IN_PROJ
#define DPJA 8704          // padded to 68*128 for GEMM tiles
#define CK   256           // CHUNK
#define NCH  32            // total chunks
#define RW   8192          // total rows = B*L

// ---------------- scratch (device globals; no allocations) ----------------
__device__ __half g_zxh[(size_t)RW * DPJA];    // in-proj output (fp16)
__device__ __half g_xBC[(size_t)RW * CD];      // conv+silu output (fp16)
__device__ float g_dt[RW * NH];
__device__ float g_dacs[RW * NH];
__device__ float g_CBt[NCH * CK * CK];
__device__ float g_states[(size_t)NCH * NH * DH * NS];
__device__ __half g_prev[(size_t)NCH * NH * DH * NS];
__device__ __half g_y[(size_t)RW * DI];
// fp16 GEMM operands
__device__ __half g_uh[(size_t)RW * DM];
__device__ __half g_wi1[(size_t)DPJA * DM];
__device__ __half g_yh[(size_t)RW * DI];
__device__ __half g_wo1[(size_t)DM * DI];

// ================= PTX helpers =================
__device__ __forceinline__ uint32_t smem_u32(const void* p) {
    uint32_t a;
    asm("{ .reg .u64 t; cvta.to.shared.u64 t, %1; cvt.u32.u64 %0, t; }" : "=r"(a) : "l"(p));
    return a;
}
#define CPA16(dst, src) \
    asm volatile("cp.async.cg.shared.global [%0], [%1], 16;" :: "r"(dst), "l"(src) : "memory")

#define LDSM4(r, adr)                                                            \
    asm volatile("ldmatrix.sync.aligned.m8n8.x4.shared.b16 {%0,%1,%2,%3}, [%4];" \
        : "=r"((r)[0]), "=r"((r)[1]), "=r"((r)[2]), "=r"((r)[3]) : "r"(adr))

#define MMAF16(c, a, b0, b1)                                                     \
    asm volatile("mma.sync.aligned.m16n8k16.row.col.f32.f16.f16.f32 "            \
        "{%0,%1,%2,%3}, {%4,%5,%6,%7}, {%8,%9}, {%0,%1,%2,%3};"                  \
        : "+f"((c)[0]), "+f"((c)[1]), "+f"((c)[2]), "+f"((c)[3])                  \
        : "r"((a)[0]), "r"((a)[1]), "r"((a)[2]), "r"((a)[3]), "r"(b0), "r"(b1))

// ================= conversion kernels =================
__global__ __launch_bounds__(256) void cvt_h1_kernel(
    const float* __restrict__ src, __half* __restrict__ dst, long n4)
{
    long i = (long)blockIdx.x * 256 + threadIdx.x;
    if (i >= n4) return;
    float4 v = ((const float4*)src)[i];
    ((__half2*)dst)[2*i]   = __halves2half2(__float2half_rn(v.x), __float2half_rn(v.y));
    ((__half2*)dst)[2*i+1] = __halves2half2(__float2half_rn(v.z), __float2half_rn(v.w));
}

__global__ __launch_bounds__(256) void cvt_h1_pad_kernel(
    const float* __restrict__ src, __half* __restrict__ dst,
    long n4, long rows_src, long cols4)
{
    long i = (long)blockIdx.x * 256 + threadIdx.x;
    if (i >= n4) return;
    float4 v = make_float4(0.f, 0.f, 0.f, 0.f);
    if (i / cols4 < rows_src) v = ((const float4*)src)[i];
    ((__half2*)dst)[2*i]   = __halves2half2(__float2half_rn(v.x), __float2half_rn(v.y));
    ((__half2*)dst)[2*i+1] = __halves2half2(__float2half_rn(v.z), __float2half_rn(v.w));
}

// ================= fp16 1-pass NT GEMM, templated output (fp32 or fp16) =================
#define FSTAGES 3
#define FROWH 40
#define FTILE (128 * FROWH)
#define FSTAGE (2 * FTILE)
#define FGEMM_SMEM (FSTAGES * FSTAGE * 2)

template <bool OUTH>
__global__ __launch_bounds__(256, 2) void gemm_f16(
    const __half* __restrict__ A1, const __half* __restrict__ B1,
    void* __restrict__ Cv, int Ktot, int ldc)
{
    extern __shared__ __half fsm[];
    const int tid = threadIdx.x;
    const int wid = tid >> 5;
    const int lane = tid & 31;

    const int m0 = blockIdx.y * 128;
    const int n0 = blockIdx.x * 128;

    const int lrow = tid >> 2;
    const int lch  = (tid & 3) * 8;

    const __half* a1p = A1 + (size_t)m0 * Ktot;
    const __half* b1p = B1 + (size_t)n0 * Ktot;

    auto load_stage = [&](int s, int k0) {
        __half* st = fsm + s * FSTAGE;
#pragma unroll
        for (int q = 0; q < 2; q++) {
            int row = lrow + q * 64;
            uint32_t d = smem_u32(st + row * FROWH + lch);
            CPA16(d,             a1p + (size_t)row * Ktot + k0 + lch);
            CPA16(d + FTILE * 2, b1p + (size_t)row * Ktot + k0 + lch);
        }
        asm volatile("cp.async.commit_group;" ::: "memory");
    };

    const int wm = (wid & 1) * 64;
    const int wn = (wid >> 1) * 32;
    const int fr = lane & 15;
    const int fch = (lane >> 4) * 8;

    float acc[4][4][4];
#pragma unroll
    for (int a = 0; a < 4; a++)
#pragma unroll
        for (int b = 0; b < 4; b++)
#pragma unroll
            for (int c = 0; c < 4; c++) acc[a][b][c] = 0.f;

    const int KT = Ktot / 32;
    load_stage(0, 0);
    load_stage(1, 32);

    int cur = 0, nxt = 2;
    for (int kt = 0; kt < KT; kt++) {
        if (kt < KT - 1) {
            asm volatile("cp.async.wait_group 1;" ::: "memory");
        } else {
            asm volatile("cp.async.wait_group 0;" ::: "memory");
        }
        __syncthreads();
        if (kt + 2 < KT) load_stage(nxt, (kt + 2) * 32);

        const __half* st = fsm + cur * FSTAGE;
#pragma unroll
        for (int kk = 0; kk < 2; kk++) {
            const int kof = kk * 16;
            uint32_t af[4][4];
#pragma unroll
            for (int mb = 0; mb < 4; mb++) {
                uint32_t adr = smem_u32(st + (wm + mb * 16 + fr) * FROWH + kof + fch);
                LDSM4(af[mb], adr);
            }
            uint32_t bf[2][4];
#pragma unroll
            for (int nb2 = 0; nb2 < 2; nb2++) {
                uint32_t adr = smem_u32(st + FTILE + (wn + nb2 * 16 + fr) * FROWH + kof + fch);
                LDSM4(bf[nb2], adr);
            }
#pragma unroll
            for (int mb = 0; mb < 4; mb++)
#pragma unroll
                for (int nb = 0; nb < 4; nb++)
                    MMAF16(acc[mb][nb], af[mb], bf[nb >> 1][nb & 1], bf[nb >> 1][(nb & 1) + 2]);
        }
        cur = (cur == 2) ? 0 : cur + 1;
        nxt = (nxt == 2) ? 0 : nxt + 1;
    }

    const int er = lane >> 2;
    const int ec = (lane & 3) * 2;
#pragma unroll
    for (int mb = 0; mb < 4; mb++) {
#pragma unroll
        for (int nb = 0; nb < 4; nb++) {
            const size_t r0 = (size_t)(m0 + wm + mb * 16 + er) * ldc + n0 + wn + nb * 8 + ec;
            const size_t r1 = r0 + (size_t)8 * ldc;
            if (OUTH) {
                __half* C = (__half*)Cv;
                *(__half2*)&C[r0] = __halves2half2(__float2half_rn(acc[mb][nb][0]),
                                                   __float2half_rn(acc[mb][nb][1]));
                *(__half2*)&C[r1] = __halves2half2(__float2half_rn(acc[mb][nb][2]),
                                                   __float2half_rn(acc[mb][nb][3]));
            } else {
                float* C = (float*)Cv;
                *(float2*)&C[r0] = make_float2(acc[mb][nb][0], acc[mb][nb][1]);
                *(float2*)&C[r1] = make_float2(acc[mb][nb][2], acc[mb][nb][3]);
            }
        }
    }
}

// ---------------- per-chunk CBt via fp16 MMA ----------------
// CBt[j][i] = sum_n B[j][n] * C[i][n]; grid (2, NCH): 128 j-rows x 256 i-cols per CTA.
#define CBT_SMEM ((128*136 + 256*136) * 2)    // 104448 bytes

__global__ __launch_bounds__(256, 1) void cbt_tc()
{
    extern __shared__ __half csm[];
    __half* Bs = csm;                 // [128][136]
    __half* Cs = csm + 128 * 136;     // [256][136]

    const int chunk = blockIdx.y, j0 = blockIdx.x * 128, base = chunk * CK;
    const int tid = threadIdx.x;

#pragma unroll
    for (int e = 0; e < 8; e++) {
        int idx = tid + e * 256;           // 2048 uint4
        int r = idx >> 4, c8 = (idx & 15) * 8;
        *(uint4*)&Bs[r * 136 + c8] =
            *(const uint4*)&g_xBC[(size_t)(base + j0 + r) * CD + DI + c8];
    }
#pragma unroll
    for (int e = 0; e < 16; e++) {
        int idx = tid + e * 256;           // 4096 uint4
        int r = idx >> 4, c8 = (idx & 15) * 8;
        *(uint4*)&Cs[r * 136 + c8] =
            *(const uint4*)&g_xBC[(size_t)(base + r) * CD + DI + NS + c8];
    }
    __syncthreads();

    const int wid = tid >> 5, lane = tid & 31;
    const int wm = (wid & 1) * 64;         // j
    const int wn = (wid >> 1) * 64;        // i
    const int fr = lane & 15, fch = (lane >> 4) * 8;

    float acc[4][8][4];
#pragma unroll
    for (int a = 0; a < 4; a++)
#pragma unroll
        for (int b = 0; b < 8; b++)
#pragma unroll
            for (int c = 0; c < 4; c++) acc[a][b][c] = 0.f;

#pragma unroll
    for (int ks = 0; ks < 8; ks++) {
        uint32_t af[4][4];
#pragma unroll
        for (int mb = 0; mb < 4; mb++)
            LDSM4(af[mb], smem_u32(Bs + (wm + mb * 16 + fr) * 136 + ks * 16 + fch));
        uint32_t bf[4][4];
#pragma unroll
        for (int nb2 = 0; nb2 < 4; nb2++)
            LDSM4(bf[nb2], smem_u32(Cs + (wn + nb2 * 16 + fr) * 136 + ks * 16 + fch));
#pragma unroll
        for (int mb = 0; mb < 4; mb++)
#pragma unroll
            for (int nb = 0; nb < 8; nb++)
                MMAF16(acc[mb][nb], af[mb], bf[nb >> 1][nb & 1], bf[nb >> 1][(nb & 1) + 2]);
    }

    float* cbt = g_CBt + (size_t)chunk * CK * CK;
    const int er = lane >> 2, ec = (lane & 3) * 2;
#pragma unroll
    for (int mb = 0; mb < 4; mb++) {
        int j = j0 + wm + mb * 16 + er;
#pragma unroll
        for (int nb = 0; nb < 8; nb++) {
            int i = wn + nb * 8 + ec;
            *(float2*)&cbt[(size_t)j * CK + i] = make_float2(acc[mb][nb][0], acc[mb][nb][1]);
            *(float2*)&cbt[(size_t)(j + 8) * CK + i] = make_float2(acc[mb][nb][2], acc[mb][nb][3]);
        }
    }
}

// ---------------- tiled causal depthwise conv (width 4) + SiLU (fp16 in/out) ----------------
#define CT_ROWS 16
__global__ __launch_bounds__(256) void conv_silu_kernel(const float* __restrict__ conv_w,
                                                        const float* __restrict__ conv_b)
{
    __shared__ float ts[CT_ROWS + 3][256];
    const int c0 = blockIdx.x * 256;
    const int r0 = blockIdx.y * CT_ROWS;
    const int tid = threadIdx.x;
    const int cc = c0 + tid;
    const int batch_start = r0 & ~(L_ - 1);

    const __half* src = g_zxh + DI + cc;
#pragma unroll
    for (int rr = 0; rr < CT_ROWS + 3; rr++) {
        int x = r0 - 3 + rr;
        ts[rr][tid] = (x >= batch_start) ? __half2float(src[(size_t)x * DPJA]) : 0.f;
    }
    __syncthreads();

    const float cw0 = conv_w[cc*4+0], cw1 = conv_w[cc*4+1];
    const float cw2 = conv_w[cc*4+2], cw3 = conv_w[cc*4+3];
    const float cb = conv_b[cc];
#pragma unroll
    for (int rr = 0; rr < CT_ROWS; rr++) {
        float acc = cb + ts[rr][tid]*cw0 + ts[rr+1][tid]*cw1
                       + ts[rr+2][tid]*cw2 + ts[rr+3][tid]*cw3;
        float s = acc / (1.0f + __expf(-acc));
        g_xBC[(size_t)(r0 + rr) * CD + cc] = __float2half_rn(s);
    }
}

// ---------------- dt softplus + within-chunk cumsum (parallel scan) ----------------
__global__ __launch_bounds__(256) void dt_cumsum_kernel(const float* __restrict__ dt_bias,
                                                        const float* __restrict__ A_log)
{
    __shared__ float wsum[8];
    const int chunk = blockIdx.x;
    const int h = blockIdx.y;
    const int i = threadIdx.x;
    const int lane = i & 31, wid = i >> 5;
    const int r = chunk * CK + i;

    float Ahd = -expf(A_log[h]);
    float x = __half2float(g_zxh[(size_t)r * DPJA + DI + CD + h]) + dt_bias[h];
    float dt = fmaxf(x, 0.f) + log1pf(expf(-fabsf(x)));
    g_dt[r*NH + h] = dt;

    float v = dt * Ahd;
#pragma unroll
    for (int o = 1; o < 32; o <<= 1) {
        float n = __shfl_up_sync(0xffffffffu, v, o);
        if (lane >= o) v += n;
    }
    if (lane == 31) wsum[wid] = v;
    __syncthreads();
    float add = 0.f;
#pragma unroll
    for (int wq = 0; wq < 8; wq++) {
        float ws = wsum[wq];
        add += (wq < wid) ? ws : 0.f;
    }
    g_dacs[r*NH + h] = v + add;
}

// ---------------- states via fp16 MMA ----------------
#define ST_SMEM (1024 + 64*264*2 + 128*264*2)

__global__ __launch_bounds__(256, 2) void states_tc()
{
    extern __shared__ char sm0[];
    float* ws = (float*)sm0;
    __half* At = (__half*)(sm0 + 1024);
    __half* Bt = (__half*)(sm0 + 1024 + 64*264*2);

    const int chunk = blockIdx.x, h = blockIdx.y, base = chunk * CK;
    const int tid = threadIdx.x;

    {
        float dl = g_dacs[(base + CK - 1)*NH + h];
        float dv = g_dacs[(base + tid)*NH + h];
        ws[tid] = __expf(dl - dv) * g_dt[(base + tid)*NH + h];
    }
    __syncthreads();

#pragma unroll 4
    for (int e = 0; e < 64; e++) {
        int idx = tid + e * 256;
        int p = idx & 63, s = idx >> 6;
        float x = __half2float(g_xBC[(size_t)(base + s) * CD + h * 64 + p]);
        At[p * 264 + s] = __float2half_rn(ws[s] * x);
    }
#pragma unroll 4
    for (int e = 0; e < 128; e++) {
        int idx = tid + e * 256;
        int n = idx & 127, s = idx >> 7;
        Bt[n * 264 + s] = g_xBC[(size_t)(base + s) * CD + DI + n];
    }
    __syncthreads();

    const int wid = tid >> 5, lane = tid & 31;
    const int wm = (wid & 1) * 32;
    const int wn = (wid >> 1) * 32;
    const int fr = lane & 15, fch = (lane >> 4) * 8;

    float acc[2][4][4];
#pragma unroll
    for (int a = 0; a < 2; a++)
#pragma unroll
        for (int b = 0; b < 4; b++)
#pragma unroll
            for (int c = 0; c < 4; c++) acc[a][b][c] = 0.f;

#pragma unroll
    for (int ks = 0; ks < 16; ks++) {
        uint32_t af[2][4];
#pragma unroll
        for (int mb = 0; mb < 2; mb++)
            LDSM4(af[mb], smem_u32(At + (wm + mb * 16 + fr) * 264 + ks * 16 + fch));
        uint32_t bf[2][4];
#pragma unroll
        for (int nb2 = 0; nb2 < 2; nb2++)
            LDSM4(bf[nb2], smem_u32(Bt + (wn + nb2 * 16 + fr) * 264 + ks * 16 + fch));
#pragma unroll
        for (int mb = 0; mb < 2; mb++)
#pragma unroll
            for (int nb = 0; nb < 4; nb++)
                MMAF16(acc[mb][nb], af[mb], bf[nb >> 1][nb & 1], bf[nb >> 1][(nb & 1) + 2]);
    }

    size_t obase = (size_t)(chunk * NH + h) * DH * NS;
    const int er = lane >> 2, ec = (lane & 3) * 2;
#pragma unroll
    for (int mb = 0; mb < 2; mb++) {
        int p0 = wm + mb * 16 + er;
#pragma unroll
        for (int nb = 0; nb < 4; nb++) {
            int col = wn + nb * 8 + ec;
            *(float2*)&g_states[obase + (size_t)p0 * NS + col] =
                make_float2(acc[mb][nb][0], acc[mb][nb][1]);
            *(float2*)&g_states[obase + (size_t)(p0 + 8) * NS + col] =
                make_float2(acc[mb][nb][2], acc[mb][nb][3]);
        }
    }
}

// ---------------- inter-chunk scan (prev stored fp16) ----------------
__global__ void scan_kernel()
{
    int idx = blockIdx.x * 256 + threadIdx.x;
    int h = (idx >> 13) & 63;
    int b = idx >> 19;
    float s = 0.f;
    for (int c = 0; c < 16; c++) {
        size_t off = ((size_t)(b*16 + c)*NH + h)*DH*NS + (idx & 8191);
        g_prev[off] = __float2half_rn(s);
        float dec = __expf(g_dacs[(size_t)(b*L_ + c*CK + CK - 1)*NH + h]);
        s = s * dec + g_states[off];
    }
}

// ---------------- y via fp16 MMA (fp16 in/out) ----------------
#define YTC_SMEM 76288

__global__ __launch_bounds__(256, 2) void y_tc(const float* __restrict__ Dp)
{
    extern __shared__ char sm1[];
    float* das  = (float*)sm1;
    float* q    = das + 256;
    float* rqd  = q + 256;
    float* ei   = rqd + 256;
    float* Sarr = ei + 256;
    float* PP   = Sarr + 8;
    __half* xT    = (__half*)(sm1 + 4608);
    __half* prevB = (__half*)(sm1 + 38400);
    __half* Mt    = (__half*)(sm1 + 55808);

    const int chunk = blockIdx.x, h = blockIdx.y, base = chunk * CK;
    const int tid = threadIdx.x;
    const int wid = tid >> 5, lane = tid & 31;

    das[tid] = g_dacs[(base + tid)*NH + h];

#pragma unroll 4
    for (int e = 0; e < 64; e++) {
        int idx = tid + e * 256;
        int p = idx & 63, s = idx >> 6;
        xT[p * 264 + s] = g_xBC[(size_t)(base + s) * CD + h * 64 + p];
    }
    {
        size_t pb = (size_t)(chunk * NH + h) * DH * NS;
#pragma unroll 4
        for (int e = 0; e < 32; e++) {
            int idx = tid + e * 256;
            int p = idx >> 7, n = idx & 127;
            prevB[p * 136 + n] = g_prev[pb + idx];
        }
    }
    __syncthreads();
    {
        int si = tid >> 5;
        float ref = das[si * 32];
        float d = das[tid];
        q[tid]   = __expf(d - ref);
        rqd[tid] = __expf(ref - d) * g_dt[(base + tid)*NH + h];
        ei[tid]  = __expf(d);
        if (tid < 8)
            Sarr[tid] = (tid == 0) ? 1.f : __expf(das[tid*32] - das[tid*32 - 32]);
    }
    __syncthreads();
    if (tid < 64) {
        int si = tid >> 3, sj = tid & 7;
        float p = 0.f;
        if (si >= sj) {
            p = 1.f;
            for (int t = sj + 1; t <= si; t++) p *= Sarr[t];
        }
        PP[tid] = p;
    }
    __syncthreads();

    const int wm = (wid >> 1) * 64;
    const int wn = (wid & 1) * 32;
    const int fr = lane & 15, fch = (lane >> 4) * 8;

    float acc[4][4][4];
#pragma unroll
    for (int a = 0; a < 4; a++)
#pragma unroll
        for (int b = 0; b < 4; b++)
#pragma unroll
            for (int c = 0; c < 4; c++) acc[a][b][c] = 0.f;

    // ---- y_diag ----
    const float* cbb = g_CBt + (size_t)chunk * CK * CK;
    for (int jt = 0; jt < 8; jt++) {
        const int j0 = jt * 32;
        {
            const int i = tid;
            const float fq = q[i] * PP[(i >> 5) * 8 + jt];
            const float* cbp = cbb + (size_t)j0 * CK + i;
            __half2* mrow = (__half2*)(Mt + i * 40);
#pragma unroll
            for (int jp = 0; jp < 16; jp++) {
                int j  = 2 * jp;
                int jj = j0 + j;
                float v0 = (jj     <= i) ? cbp[(size_t)j * CK]     * fq * rqd[jj]     : 0.f;
                float v1 = (jj + 1 <= i) ? cbp[(size_t)(j+1) * CK] * fq * rqd[jj + 1] : 0.f;
                mrow[jp] = __halves2half2(__float2half_rn(v0), __float2half_rn(v1));
            }
        }
        __syncthreads();
        if (j0 < wm + 64) {
#pragma unroll
            for (int kk = 0; kk < 2; kk++) {
                uint32_t af[4][4];
#pragma unroll
                for (int mb = 0; mb < 4; mb++)
                    LDSM4(af[mb], smem_u32(Mt + (wm + mb * 16 + fr) * 40 + kk * 16 + fch));
                uint32_t bf[2][4];
#pragma unroll
                for (int nb2 = 0; nb2 < 2; nb2++)
                    LDSM4(bf[nb2], smem_u32(xT + (wn + nb2 * 16 + fr) * 264 + j0 + kk * 16 + fch));
#pragma unroll
                for (int mb = 0; mb < 4; mb++)
#pragma unroll
                    for (int nb = 0; nb < 4; nb++)
                        MMAF16(acc[mb][nb], af[mb], bf[nb >> 1][nb & 1], bf[nb >> 1][(nb & 1) + 2]);
            }
        }
        __syncthreads();
    }

    // ---- y_off ----
    for (int nt = 0; nt < 4; nt++) {
        const int n0 = nt * 32;
        {
            const int i = tid;
            const float e = ei[i];
            const __half2* cp2 = (const __half2*)&g_xBC[(size_t)(base + i) * CD + DI + NS + n0];
            __half2* mrow = (__half2*)(Mt + i * 40);
#pragma unroll
            for (int j2 = 0; j2 < 16; j2++) {
                __half2 v = cp2[j2];
                mrow[j2] = __floats2half2_rn(e * __low2float(v), e * __high2float(v));
            }
        }
        __syncthreads();
#pragma unroll
        for (int kk = 0; kk < 2; kk++) {
            uint32_t af[4][4];
#pragma unroll
            for (int mb = 0; mb < 4; mb++)
                LDSM4(af[mb], smem_u32(Mt + (wm + mb * 16 + fr) * 40 + kk * 16 + fch));
            uint32_t bf[2][4];
#pragma unroll
            for (int nb2 = 0; nb2 < 2; nb2++)
                LDSM4(bf[nb2], smem_u32(prevB + (wn + nb2 * 16 + fr) * 136 + n0 + kk * 16 + fch));
#pragma unroll
            for (int mb = 0; mb < 4; mb++)
#pragma unroll
                for (int nb = 0; nb < 4; nb++)
                    MMAF16(acc[mb][nb], af[mb], bf[nb >> 1][nb & 1], bf[nb >> 1][(nb & 1) + 2]);
        }
        __syncthreads();
    }

    // ---- epilogue: y = acc + Dp[h] * x  (fp16 store) ----
    const float dph = Dp[h];
    const int er = lane >> 2, ec = (lane & 3) * 2;
#pragma unroll
    for (int mb = 0; mb < 4; mb++) {
        int i0 = wm + mb * 16 + er;
#pragma unroll
        for (int nb = 0; nb < 4; nb++) {
            int p = wn + nb * 8 + ec;
            float x00 = __half2float(xT[(size_t)p * 264 + i0]);
            float x01 = __half2float(xT[(size_t)(p + 1) * 264 + i0]);
            float x10 = __half2float(xT[(size_t)p * 264 + i0 + 8]);
            float x11 = __half2float(xT[(size_t)(p + 1) * 264 + i0 + 8]);
            *(__half2*)&g_y[(size_t)(base + i0) * DI + h * 64 + p] =
                __halves2half2(__float2half_rn(acc[mb][nb][0] + dph * x00),
                               __float2half_rn(acc[mb][nb][1] + dph * x01));
            *(__half2*)&g_y[(size_t)(base + i0 + 8) * DI + h * 64 + p] =
                __halves2half2(__float2half_rn(acc[mb][nb][2] + dph * x10),
                               __float2half_rn(acc[mb][nb][3] + dph * x11));
        }
    }
}

// ---------------- gate (silu(z)) + RMSNorm; fp16 in/out ----------------
__global__ __launch_bounds__(256) void gate_norm_kernel(const float* __restrict__ norm_w)
{
    __shared__ float buf[DI];
    __shared__ float red[8];
    int r = blockIdx.x;
    int tid = threadIdx.x;
    float ss = 0.f;
#pragma unroll
    for (int e = 0; e < 16; e++) {
        int c = tid + e*256;
        float y = __half2float(g_y[(size_t)r*DI + c]);
        float z = __half2float(g_zxh[(size_t)r*DPJA + c]);
        float g = y * (z / (1.f + __expf(-z)));
        buf[c] = g;
        ss += g*g;
    }
#pragma unroll
    for (int o = 16; o > 0; o >>= 1) ss += __shfl_xor_sync(0xffffffffu, ss, o);
    if ((tid & 31) == 0) red[tid >> 5] = ss;
    __syncthreads();
    float tot = 0.f;
#pragma unroll
    for (int q = 0; q < 8; q++) tot += red[q];
    float scale = rsqrtf(tot / (float)DI + 1e-5f);
#pragma unroll
    for (int e = 0; e < 16; e++) {
        int c = tid + e*256;
        g_yh[(size_t)r*DI + c] = __float2half_rn(buf[c] * scale * norm_w[c]);
    }
}

// ---------------- launch ----------------
extern "C" void kernel_launch(void* const* d_in, const int* in_sizes, int n_in,
                              void* d_out, int out_size)
{
    const float* u       = (const float*)d_in[0];
    const float* W_in    = (const float*)d_in[1];
    const float* conv_w  = (const float*)d_in[2];
    const float* conv_b  = (const float*)d_in[3];
    const float* dt_bias = (const float*)d_in[4];
    const float* A_log   = (const float*)d_in[5];
    const float* Dp      = (const float*)d_in[6];
    const float* norm_w  = (const float*)d_in[7];
    const float* W_out   = (const float*)d_in[8];
    float* out = (float*)d_out;

    __half *zxh, *uh, *wi1, *yh, *wo1;
    cudaGetSymbolAddress((void**)&zxh, g_zxh);
    cudaGetSymbolAddress((void**)&uh,  g_uh);
    cudaGetSymbolAddress((void**)&wi1, g_wi1);
    cudaGetSymbolAddress((void**)&yh,  g_yh);
    cudaGetSymbolAddress((void**)&wo1, g_wo1);

    cudaFuncSetAttribute(gemm_f16<true>,  cudaFuncAttributeMaxDynamicSharedMemorySize, FGEMM_SMEM);
    cudaFuncSetAttribute(gemm_f16<false>, cudaFuncAttributeMaxDynamicSharedMemorySize, FGEMM_SMEM);
    cudaFuncSetAttribute(cbt_tc,    cudaFuncAttributeMaxDynamicSharedMemorySize, CBT_SMEM);
    cudaFuncSetAttribute(states_tc, cudaFuncAttributeMaxDynamicSharedMemorySize, ST_SMEM);
    cudaFuncSetAttribute(y_tc,      cudaFuncAttributeMaxDynamicSharedMemorySize, YTC_SMEM);

    // convert inputs for GEMM1
    {
        long n4 = (long)RW * DM / 4;
        cvt_h1_kernel<<<(int)((n4 + 255) / 256), 256>>>(u, uh, n4);
    }
    {
        long n4 = (long)DPJA * DM / 4;
        cvt_h1_pad_kernel<<<(int)((n4 + 255) / 256), 256>>>(W_in, wi1, n4, DPJ, DM/4);
    }

    // 1) in-proj (fp16 GEMM, fp16 output)
    gemm_f16<true><<<dim3(DPJA/128, RW/128), 256, FGEMM_SMEM>>>(uh, wi1, zxh, DM, DPJA);

    // 2) conv + silu (fp16 in/out)
    conv_silu_kernel<<<dim3(CD/256, RW/CT_ROWS), 256>>>(conv_w, conv_b);

    // 3) dt softplus + per-chunk cumsum
    dt_cumsum_kernel<<<dim3(NCH, NH), 256>>>(dt_bias, A_log);

    // 4) per-chunk CBt (fp16 MMA)
    cbt_tc<<<dim3(2, NCH), 256, CBT_SMEM>>>();

    // 5) states (fp16 MMA)
    states_tc<<<dim3(NCH, NH), 256, ST_SMEM>>>();

    // 6) inter-chunk scan (fp16 prev out)
    scan_kernel<<<4096, 256>>>();

    // 7) fused y (fp16 MMA)
    y_tc<<<dim3(NCH, NH), 256, YTC_SMEM>>>(Dp);

    // 8) gate + RMSNorm
    gate_norm_kernel<<<RW, 256>>>(norm_w);

    // convert W_out for GEMM2
    {
        long n4 = (long)DM * DI / 4;
        cvt_h1_kernel<<<(int)((n4 + 255) / 256), 256>>>(W_out, wo1, n4);
    }

    // 9) out-proj (fp16 GEMM, fp32 output)
    gemm_f16<false><<<dim3(DM/128, RW/128), 256, FGEMM_SMEM>>>(yh, wo1, out, DI, DM);
}